// round 10
// baseline (speedup 1.0000x reference)
#include <cuda_runtime.h>
#include <cuda_bf16.h>
#include <cstdint>

// ---------------------------------------------------------------------------
// SpectralMSA channel attention — Round 10: 4-stage k16 cp.async pipeline.
//   Pre-split bf16 operands (R8). GEMM mainloop: 4-stage cp.async ring
//   (k16/stage, wait_group 2 -> 2 stages always in flight), [row][k] smem,
//   48B rows (LDSM conflict-free), ldmatrix.x4, stage offsets compile-time.
//   logits/pv on mma.sync (R7/R8 winners).
// ---------------------------------------------------------------------------

namespace {
constexpr int kB = 4;
constexpr int kN = 4096;
constexpr int kC = 1024;
constexpr int kH = 16;
constexpr int kD = 64;
constexpr int kM = kB * kN;        // 16384
constexpr int kQKV = 3 * kC;       // 3072
constexpr int kSplits = 8;
}

// fp32 scratch
__device__ float g_qkv[(size_t)3 * kB * kH * kN * kD];   // [sel][b][h][n][d]
__device__ float g_attn[(size_t)kSplits * kB * kH * kD * kD];
__device__ float g_attnP[(size_t)kB * kH * kD * kD];
// split-bf16 operands
__device__ __nv_bfloat16 g_xH[(size_t)kM * kC],      g_xL[(size_t)kM * kC];
__device__ __nv_bfloat16 g_wqkvH[(size_t)kQKV * kC], g_wqkvL[(size_t)kQKV * kC];
__device__ __nv_bfloat16 g_wprojH[(size_t)kC * kC],  g_wprojL[(size_t)kC * kC];
__device__ __nv_bfloat16 g_outH[(size_t)kM * kC],    g_outL[(size_t)kM * kC];

// ---------------- low-level helpers ----------------------------------------
__device__ __forceinline__ void mma_bf16(float& d0, float& d1, float& d2, float& d3,
                                         unsigned a0, unsigned a1, unsigned a2, unsigned a3,
                                         unsigned b0, unsigned b1)
{
    asm volatile(
        "mma.sync.aligned.m16n8k16.row.col.f32.bf16.bf16.f32 "
        "{%0,%1,%2,%3},{%4,%5,%6,%7},{%8,%9},{%0,%1,%2,%3};"
        : "+f"(d0), "+f"(d1), "+f"(d2), "+f"(d3)
        : "r"(a0), "r"(a1), "r"(a2), "r"(a3), "r"(b0), "r"(b1));
}

__device__ __forceinline__ void split2pack(float a, float b, unsigned& h, unsigned& l)
{
    __nv_bfloat16 ha = __float2bfloat16_rn(a), hb = __float2bfloat16_rn(b);
    __nv_bfloat162 ph(ha, hb); h = *(unsigned*)&ph;
    __nv_bfloat162 pl(__float2bfloat16_rn(a - __bfloat162float(ha)),
                      __float2bfloat16_rn(b - __bfloat162float(hb)));
    l = *(unsigned*)&pl;
}

// 3-product accumulate: HL + LH + HH
__device__ __forceinline__ void mma3(float* acc,
                                     const unsigned aH[4], const unsigned aL[4],
                                     unsigned bH0, unsigned bH1,
                                     unsigned bL0, unsigned bL1)
{
    mma_bf16(acc[0], acc[1], acc[2], acc[3], aH[0], aH[1], aH[2], aH[3], bL0, bL1);
    mma_bf16(acc[0], acc[1], acc[2], acc[3], aL[0], aL[1], aL[2], aL[3], bH0, bH1);
    mma_bf16(acc[0], acc[1], acc[2], acc[3], aH[0], aH[1], aH[2], aH[3], bH0, bH1);
}

__device__ __forceinline__ uint32_t smem_u32(const void* p) {
    uint32_t a;
    asm("{ .reg .u64 t; cvta.to.shared.u64 t, %1; cvt.u32.u64 %0, t; }"
        : "=r"(a) : "l"(p));
    return a;
}
__device__ __forceinline__ void cp16(uint32_t dst, const void* src) {
    asm volatile("cp.async.cg.shared.global [%0], [%1], 16;" :: "r"(dst), "l"(src));
}
__device__ __forceinline__ void cp_commit() {
    asm volatile("cp.async.commit_group;" ::: "memory");
}
template <int N>
__device__ __forceinline__ void cp_wait() {
    asm volatile("cp.async.wait_group %0;" :: "n"(N) : "memory");
}
__device__ __forceinline__ void ldsm4(unsigned* r, uint32_t addr) {
    asm volatile("ldmatrix.sync.aligned.m8n8.x4.shared.b16 {%0,%1,%2,%3}, [%4];"
                 : "=r"(r[0]), "=r"(r[1]), "=r"(r[2]), "=r"(r[3]) : "r"(addr));
}

// ---------------------------------------------------------------------------
__global__ void split_kernel(const float* __restrict__ src,
                             __nv_bfloat16* __restrict__ hi,
                             __nv_bfloat16* __restrict__ lo, int n4)
{
    int i = blockIdx.x * blockDim.x + threadIdx.x;
    if (i >= n4) return;
    float4 v = ((const float4*)src)[i];
    unsigned h0, h1, l0, l1;
    split2pack(v.x, v.y, h0, l0);
    split2pack(v.z, v.w, h1, l1);
    ((uint2*)hi)[i] = make_uint2(h0, h1);
    ((uint2*)lo)[i] = make_uint2(l0, l1);
}

// Epilogue write modes
enum { OUT_PLAIN_BIAS = 1, OUT_QKV_HM = 2 };

__device__ __forceinline__ void write_qkv_hm(int m, int n, float2 v)
{
    const int sel = n >> 10;
    const int h   = (n >> 6) & 15;
    const int d   = n & 63;
    const int b   = m >> 12;
    const int ntk = m & 4095;
    float* dst = g_qkv +
        ((((size_t)sel * kB + b) * kH + h) * kN + ntk) * kD + d;
    *(float2*)dst = v;
}

// ---------------------------------------------------------------------------
// bf16x3 GEMM (NT), 4-stage k16 cp.async ring + ldmatrix.
// Block 128x128, 256 thr, warp tile 64x32.
// ---------------------------------------------------------------------------
namespace {
constexpr int ROWB   = 48;               // 16 bf16 (32B) + 16B pad: LDSM conflict-free
constexpr int PLANE  = 128 * ROWB;       // 6144 B
constexpr int STAGEB = 4 * PLANE;        // 24576 B
constexpr int NSTAGE = 4;
constexpr int SMEM_GEMM = NSTAGE * STAGEB;   // 98304 B
}

template <int OUT_MODE>
__global__ __launch_bounds__(256)
void bf16x3_gemm_cp(const __nv_bfloat16* __restrict__ AH,
                    const __nv_bfloat16* __restrict__ AL,
                    const __nv_bfloat16* __restrict__ BH,
                    const __nv_bfloat16* __restrict__ BL,
                    float* __restrict__ C, const float* __restrict__ bias,
                    int M, int N, int K)
{
    extern __shared__ char sm[];
    const uint32_t sbase = smem_u32(sm);

    const int t = threadIdx.x;
    const int warp = t >> 5, lane = t & 31;
    const int wm = (warp & 1) * 64;
    const int wn = (warp >> 1) * 32;
    const int m0 = blockIdx.y * 128, n0 = blockIdx.x * 128;

    // cp loader: each thread 1 cp16 per plane: row = t>>1, chunk = t&1
    const int lrow = t >> 1, lch = t & 1;
    const uint32_t doff = lrow * ROWB + lch * 16;
    const __nv_bfloat16* pAH = AH + (size_t)(m0 + lrow) * K + lch * 8;
    const __nv_bfloat16* pAL = AL + (size_t)(m0 + lrow) * K + lch * 8;
    const __nv_bfloat16* pBH = BH + (size_t)(n0 + lrow) * K + lch * 8;
    const __nv_bfloat16* pBL = BL + (size_t)(n0 + lrow) * K + lch * 8;

    auto load_stage = [&](uint32_t stoff, int k0) {
        const uint32_t d = sbase + stoff + doff;
        cp16(d,             pAH + k0);
        cp16(d + PLANE,     pAL + k0);
        cp16(d + 2 * PLANE, pBH + k0);
        cp16(d + 3 * PLANE, pBL + k0);
    };

    float acc[4][4][4];
#pragma unroll
    for (int i = 0; i < 4; ++i)
#pragma unroll
        for (int j = 0; j < 4; ++j)
#pragma unroll
            for (int q = 0; q < 4; ++q) acc[i][j][q] = 0.f;

    // LDSM lane geometry
    const int quad = lane >> 3;
    const int l8   = lane & 7;
    const int roff = (quad & 1) * 8 + l8;
    const int koffB = (quad >> 1) * 16;

    const int nch = K / 16;              // 64

    load_stage(0 * STAGEB, 0);  cp_commit();
    load_stage(1 * STAGEB, 16); cp_commit();
    load_stage(2 * STAGEB, 32); cp_commit();

    for (int ch = 0; ch < nch; ch += 4) {
#pragma unroll
        for (int u = 0; u < 4; ++u) {
            const int cc = ch + u;
            cp_wait<2>();
            __syncthreads();

            // prefetch stage cc+3 (ring slot (u+3)&3 — compile-time)
            if (cc + 3 < nch)
                load_stage((uint32_t)(((u + 3) & 3) * STAGEB), (cc + 3) * 16);
            cp_commit();

            // compute stage u (compile-time smem offset)
            const uint32_t sb = sbase + u * STAGEB;
            unsigned aH[4][4], aL[4][4];
#pragma unroll
            for (int mt = 0; mt < 4; ++mt) {
                const uint32_t ra = sb + (wm + mt * 16 + roff) * ROWB + koffB;
                ldsm4(aH[mt], ra);
                ldsm4(aL[mt], ra + PLANE);
            }
            unsigned bfH[2][4], bfL[2][4];
#pragma unroll
            for (int pt = 0; pt < 2; ++pt) {
                const uint32_t rb = sb + 2 * PLANE
                                  + (wn + pt * 16 + roff) * ROWB + koffB;
                ldsm4(bfH[pt], rb);
                ldsm4(bfL[pt], rb + PLANE);
            }
#pragma unroll
            for (int mt = 0; mt < 4; ++mt)
#pragma unroll
                for (int nt = 0; nt < 4; ++nt) {
                    const int pt = nt >> 1, hi = nt & 1;
                    mma3(acc[mt][nt], aH[mt], aL[mt],
                         bfH[pt][hi], bfH[pt][2 + hi],
                         bfL[pt][hi], bfL[pt][2 + hi]);
                }
        }
    }

    const int r = lane >> 2, c = lane & 3;
#pragma unroll
    for (int mt = 0; mt < 4; ++mt) {
#pragma unroll
        for (int nt = 0; nt < 4; ++nt) {
            const int m = m0 + wm + mt * 16 + r;
            const int n = n0 + wn + nt * 8 + c * 2;
            float2 v0 = make_float2(acc[mt][nt][0], acc[mt][nt][1]);
            float2 v1 = make_float2(acc[mt][nt][2], acc[mt][nt][3]);
            if (OUT_MODE == OUT_QKV_HM) {
                write_qkv_hm(m, n, v0);
                write_qkv_hm(m + 8, n, v1);
            } else {
                const float b0v = bias[n], b1v = bias[n + 1];
                v0.x += b0v; v0.y += b1v;
                v1.x += b0v; v1.y += b1v;
                *(float2*)(C + (size_t)m * N + n)       = v0;
                *(float2*)(C + (size_t)(m + 8) * N + n) = v1;
            }
        }
    }
}

// ---------------------------------------------------------------------------
// Logits on tensor cores (R7 winner): partial[split][bh] = K^T Q over split-N.
// ---------------------------------------------------------------------------
__global__ __launch_bounds__(256)
void attn_logits_mma()
{
    __shared__ unsigned AH[32][72], AL[32][72];   // k^T planes
    __shared__ unsigned BH[32][72], BL[32][72];   // q^T planes

    const int t = threadIdx.x;
    const int warp = t >> 5, lane = t & 31;
    const int wm = (warp & 1) * 32;
    const int wn = (warp >> 1) * 16;
    const int r = lane >> 2, c = lane & 3;
    const int split = blockIdx.x, bh = blockIdx.y;

    const float* qb = g_qkv + (size_t)(0 * kB * kH + bh) * kN * kD;
    const float* kb = g_qkv + (size_t)(1 * kB * kH + bh) * kN * kD;

    float acc[2][2][4];
#pragma unroll
    for (int i = 0; i < 2; ++i)
#pragma unroll
        for (int j = 0; j < 2; ++j)
#pragma unroll
            for (int q = 0; q < 4; ++q) acc[i][j][q] = 0.f;

    const int nbeg = split * (kN / kSplits);
    for (int n0 = nbeg; n0 < nbeg + kN / kSplits; n0 += 64) {
#pragma unroll
        for (int i = 0; i < 4; ++i) {
            const int f = t + i * 256;
            const float* src = (f < 512) ? kb : qb;
            unsigned (*pH)[72] = (f < 512) ? AH : BH;
            unsigned (*pL)[72] = (f < 512) ? AL : BL;
            const int g  = f & 511;
            const int pr = g >> 4;
            const int d4 = (g & 15) * 4;
            const float* p0 = src + (size_t)(n0 + 2 * pr) * kD + d4;
            float4 v0 = *(const float4*)p0;
            float4 v1 = *(const float4*)(p0 + kD);
            split2pack(v0.x, v1.x, pH[pr][d4 + 0], pL[pr][d4 + 0]);
            split2pack(v0.y, v1.y, pH[pr][d4 + 1], pL[pr][d4 + 1]);
            split2pack(v0.z, v1.z, pH[pr][d4 + 2], pL[pr][d4 + 2]);
            split2pack(v0.w, v1.w, pH[pr][d4 + 3], pL[pr][d4 + 3]);
        }
        __syncthreads();

#pragma unroll
        for (int s = 0; s < 4; ++s) {
            const int base = 8 * s;
            unsigned aH[2][4], aL[2][4], bH[2][2], bL[2][2];
#pragma unroll
            for (int mt = 0; mt < 2; ++mt) {
                const int mr = wm + mt * 16 + r;
                aH[mt][0] = AH[base + c][mr];     aH[mt][1] = AH[base + c][mr + 8];
                aH[mt][2] = AH[base + c + 4][mr]; aH[mt][3] = AH[base + c + 4][mr + 8];
                aL[mt][0] = AL[base + c][mr];     aL[mt][1] = AL[base + c][mr + 8];
                aL[mt][2] = AL[base + c + 4][mr]; aL[mt][3] = AL[base + c + 4][mr + 8];
            }
#pragma unroll
            for (int nt = 0; nt < 2; ++nt) {
                const int nr = wn + nt * 8 + r;
                bH[nt][0] = BH[base + c][nr]; bH[nt][1] = BH[base + c + 4][nr];
                bL[nt][0] = BL[base + c][nr]; bL[nt][1] = BL[base + c + 4][nr];
            }
#pragma unroll
            for (int mt = 0; mt < 2; ++mt)
#pragma unroll
                for (int nt = 0; nt < 2; ++nt)
                    mma3(acc[mt][nt], aH[mt], aL[mt],
                         bH[nt][0], bH[nt][1], bL[nt][0], bL[nt][1]);
        }
        __syncthreads();
    }

    float* o = g_attn + ((size_t)split * (kB * kH) + bh) * (kD * kD);
#pragma unroll
    for (int mt = 0; mt < 2; ++mt) {
#pragma unroll
        for (int nt = 0; nt < 2; ++nt) {
            const int dr = wm + mt * 16 + r;
            const int e0 = wn + nt * 8 + 2 * c;
            *(float2*)(o + dr * kD + e0)       = make_float2(acc[mt][nt][0], acc[mt][nt][1]);
            *(float2*)(o + (dr + 8) * kD + e0) = make_float2(acc[mt][nt][2], acc[mt][nt][3]);
        }
    }
}

// ---------------------------------------------------------------------------
__global__ void softmax_kernel(const float* __restrict__ alpha)
{
    const int row = blockIdx.x;
    const int t = threadIdx.x;
    const int h = (row >> 6) & 15;
    __shared__ float s[64];

    float v = 0.f;
#pragma unroll
    for (int sp = 0; sp < kSplits; ++sp)
        v += g_attn[(size_t)sp * (kB * kH * kD * kD) + (size_t)row * kD + t];
    v /= alpha[h];

    s[t] = v;
    __syncthreads();
    for (int off = 32; off > 0; off >>= 1) {
        if (t < off) s[t] = fmaxf(s[t], s[t + off]);
        __syncthreads();
    }
    const float mx = s[0];
    __syncthreads();
    const float e = expf(v - mx);
    s[t] = e;
    __syncthreads();
    for (int off = 32; off > 0; off >>= 1) {
        if (t < off) s[t] += s[t + off];
        __syncthreads();
    }
    g_attnP[(size_t)row * kD + t] = e / s[0];
}

// ---------------------------------------------------------------------------
// P @ V^T on tensor cores (R8 winner) — epilogue writes SPLIT bf16 out.
// ---------------------------------------------------------------------------
__global__ __launch_bounds__(256)
void pv_mma()
{
    __shared__ unsigned VH[32][72], VL[32][72];
    __shared__ unsigned PH[32][72], PL[32][72];

    const int t = threadIdx.x;
    const int warp = t >> 5, lane = t & 31;
    const int wm = (warp & 1) * 32;       // token
    const int wn = (warp >> 1) * 16;      // d
    const int r = lane >> 2, c = lane & 3;
    const int tk0 = blockIdx.x * 64;
    const int bh = blockIdx.y;
    const int b = bh >> 4, h = bh & 15;

    const float* Vg = g_qkv + (size_t)(2 * kB * kH + bh) * kN * kD
                    + (size_t)tk0 * kD;
    const float* Pg = g_attnP + (size_t)bh * (kD * kD);

#pragma unroll
    for (int i = 0; i < 4; ++i) {
        const int f = t + i * 256;
        const int row = f >> 4;
        const int e4 = (f & 15) * 4;
        const int kp = e4 >> 1;
        float4 v = *(const float4*)(Vg + (size_t)row * kD + e4);
        split2pack(v.x, v.y, VH[kp][row], VL[kp][row]);
        split2pack(v.z, v.w, VH[kp + 1][row], VL[kp + 1][row]);
        float4 p = *(const float4*)(Pg + row * kD + e4);
        split2pack(p.x, p.y, PH[kp][row], PL[kp][row]);
        split2pack(p.z, p.w, PH[kp + 1][row], PL[kp + 1][row]);
    }
    __syncthreads();

    float acc[2][2][4];
#pragma unroll
    for (int i = 0; i < 2; ++i)
#pragma unroll
        for (int j = 0; j < 2; ++j)
#pragma unroll
            for (int q = 0; q < 4; ++q) acc[i][j][q] = 0.f;

#pragma unroll
    for (int s = 0; s < 4; ++s) {
        const int base = 8 * s;
        unsigned aH[2][4], aL[2][4], bH[2][2], bL[2][2];
#pragma unroll
        for (int mt = 0; mt < 2; ++mt) {
            const int mr = wm + mt * 16 + r;
            aH[mt][0] = VH[base + c][mr];     aH[mt][1] = VH[base + c][mr + 8];
            aH[mt][2] = VH[base + c + 4][mr]; aH[mt][3] = VH[base + c + 4][mr + 8];
            aL[mt][0] = VL[base + c][mr];     aL[mt][1] = VL[base + c][mr + 8];
            aL[mt][2] = VL[base + c + 4][mr]; aL[mt][3] = VL[base + c + 4][mr + 8];
        }
#pragma unroll
        for (int nt = 0; nt < 2; ++nt) {
            const int nr = wn + nt * 8 + r;
            bH[nt][0] = PH[base + c][nr]; bH[nt][1] = PH[base + c + 4][nr];
            bL[nt][0] = PL[base + c][nr]; bL[nt][1] = PL[base + c + 4][nr];
        }
#pragma unroll
        for (int mt = 0; mt < 2; ++mt)
#pragma unroll
            for (int nt = 0; nt < 2; ++nt)
                mma3(acc[mt][nt], aH[mt], aL[mt],
                     bH[nt][0], bH[nt][1], bL[nt][0], bL[nt][1]);
    }

    // epilogue: split out[token][channel] directly into bf16 hi/lo arrays
#pragma unroll
    for (int mt = 0; mt < 2; ++mt) {
#pragma unroll
        for (int nt = 0; nt < 2; ++nt) {
            const int tok = tk0 + wm + mt * 16 + r;
            const int ch = h * kD + wn + nt * 8 + 2 * c;       // even
            const size_t i0 = (((size_t)b * kN + tok) * kC + ch) >> 1;
            const size_t i1 = (((size_t)b * kN + tok + 8) * kC + ch) >> 1;
            unsigned hw, lw;
            split2pack(acc[mt][nt][0], acc[mt][nt][1], hw, lw);
            ((unsigned*)g_outH)[i0] = hw;
            ((unsigned*)g_outL)[i0] = lw;
            split2pack(acc[mt][nt][2], acc[mt][nt][3], hw, lw);
            ((unsigned*)g_outH)[i1] = hw;
            ((unsigned*)g_outL)[i1] = lw;
        }
    }
}

// ---------------------------------------------------------------------------
extern "C" void kernel_launch(void* const* d_in, const int* in_sizes, int n_in,
                              void* d_out, int out_size)
{
    const float* x = nullptr;
    const float* Wqkv = nullptr;
    const float* Wproj = nullptr;
    const float* bproj = nullptr;
    const float* alpha = nullptr;
    for (int i = 0; i < n_in; ++i) {
        switch (in_sizes[i]) {
            case kM * kC:    x     = (const float*)d_in[i]; break;
            case kQKV * kC:  Wqkv  = (const float*)d_in[i]; break;
            case kC * kC:    Wproj = (const float*)d_in[i]; break;
            case kC:         bproj = (const float*)d_in[i]; break;
            case kH:         alpha = (const float*)d_in[i]; break;
            default: break;
        }
    }

    __nv_bfloat16 *xH, *xL, *wqH, *wqL, *wpH, *wpL, *oH, *oL;
    cudaGetSymbolAddress((void**)&xH, g_xH);     cudaGetSymbolAddress((void**)&xL, g_xL);
    cudaGetSymbolAddress((void**)&wqH, g_wqkvH); cudaGetSymbolAddress((void**)&wqL, g_wqkvL);
    cudaGetSymbolAddress((void**)&wpH, g_wprojH); cudaGetSymbolAddress((void**)&wpL, g_wprojL);
    cudaGetSymbolAddress((void**)&oH, g_outH);   cudaGetSymbolAddress((void**)&oL, g_outL);

    cudaFuncSetAttribute(bf16x3_gemm_cp<OUT_QKV_HM>,
                         cudaFuncAttributeMaxDynamicSharedMemorySize, SMEM_GEMM);
    cudaFuncSetAttribute(bf16x3_gemm_cp<OUT_PLAIN_BIAS>,
                         cudaFuncAttributeMaxDynamicSharedMemorySize, SMEM_GEMM);

    // 0) pre-split GEMM operands
    {
        int n4 = kM * kC / 4;
        split_kernel<<<(n4 + 255) / 256, 256>>>(x, xH, xL, n4);
        n4 = kQKV * kC / 4;
        split_kernel<<<(n4 + 255) / 256, 256>>>(Wqkv, wqH, wqL, n4);
        n4 = kC * kC / 4;
        split_kernel<<<(n4 + 255) / 256, 256>>>(Wproj, wpH, wpL, n4);
    }

    // 1) QKV projection -> head-major qkv
    dim3 g1(kQKV / 128, kM / 128);
    bf16x3_gemm_cp<OUT_QKV_HM><<<g1, 256, SMEM_GEMM>>>(
        xH, xL, wqH, wqL, nullptr, nullptr, kM, kQKV, kC);

    // 2) Channel-attention logits on tensor cores
    attn_logits_mma<<<dim3(kSplits, kB * kH), 256>>>();

    // 3) Softmax
    softmax_kernel<<<kB * kH * kD, kD>>>(alpha);

    // 4) P @ V^T on tensor cores (emits split bf16 out)
    pv_mma<<<dim3(kN / 64, kB * kH), 256>>>();

    // 5) Output projection + bias
    dim3 g3(kC / 128, kM / 128);
    bf16x3_gemm_cp<OUT_PLAIN_BIAS><<<g3, 256, SMEM_GEMM>>>(
        oH, oL, wpH, wpL, (float*)d_out, bproj, kM, kC, kC);
}

// round 11
// speedup vs baseline: 1.3171x; 1.3171x over previous
#include <cuda_runtime.h>
#include <cuda_bf16.h>
#include <cstdint>

// ---------------------------------------------------------------------------
// SpectralMSA channel attention — Round 11: 3-stage k32 cp.async ring with
// wait_group<1> (2 chunks of compute to hide each stage's gmem latency) and
// XOR-swizzled 64B rows (LDSM conflict-free, no pad -> 96KB/CTA, 2 CTA/SM).
// Barrier count unchanged vs R9 (one per k32). Everything else = R9 winners.
// ---------------------------------------------------------------------------

namespace {
constexpr int kB = 4;
constexpr int kN = 4096;
constexpr int kC = 1024;
constexpr int kH = 16;
constexpr int kD = 64;
constexpr int kM = kB * kN;        // 16384
constexpr int kQKV = 3 * kC;       // 3072
constexpr int kSplits = 8;
}

// fp32 scratch
__device__ float g_qkv[(size_t)3 * kB * kH * kN * kD];   // [sel][b][h][n][d]
__device__ float g_attn[(size_t)kSplits * kB * kH * kD * kD];
__device__ float g_attnP[(size_t)kB * kH * kD * kD];
// split-bf16 operands
__device__ __nv_bfloat16 g_xH[(size_t)kM * kC],      g_xL[(size_t)kM * kC];
__device__ __nv_bfloat16 g_wqkvH[(size_t)kQKV * kC], g_wqkvL[(size_t)kQKV * kC];
__device__ __nv_bfloat16 g_wprojH[(size_t)kC * kC],  g_wprojL[(size_t)kC * kC];
__device__ __nv_bfloat16 g_outH[(size_t)kM * kC],    g_outL[(size_t)kM * kC];

// ---------------- low-level helpers ----------------------------------------
__device__ __forceinline__ void mma_bf16(float& d0, float& d1, float& d2, float& d3,
                                         unsigned a0, unsigned a1, unsigned a2, unsigned a3,
                                         unsigned b0, unsigned b1)
{
    asm volatile(
        "mma.sync.aligned.m16n8k16.row.col.f32.bf16.bf16.f32 "
        "{%0,%1,%2,%3},{%4,%5,%6,%7},{%8,%9},{%0,%1,%2,%3};"
        : "+f"(d0), "+f"(d1), "+f"(d2), "+f"(d3)
        : "r"(a0), "r"(a1), "r"(a2), "r"(a3), "r"(b0), "r"(b1));
}

__device__ __forceinline__ void split2pack(float a, float b, unsigned& h, unsigned& l)
{
    __nv_bfloat16 ha = __float2bfloat16_rn(a), hb = __float2bfloat16_rn(b);
    __nv_bfloat162 ph(ha, hb); h = *(unsigned*)&ph;
    __nv_bfloat162 pl(__float2bfloat16_rn(a - __bfloat162float(ha)),
                      __float2bfloat16_rn(b - __bfloat162float(hb)));
    l = *(unsigned*)&pl;
}

// 3-product accumulate: HL + LH + HH
__device__ __forceinline__ void mma3(float* acc,
                                     const unsigned aH[4], const unsigned aL[4],
                                     unsigned bH0, unsigned bH1,
                                     unsigned bL0, unsigned bL1)
{
    mma_bf16(acc[0], acc[1], acc[2], acc[3], aH[0], aH[1], aH[2], aH[3], bL0, bL1);
    mma_bf16(acc[0], acc[1], acc[2], acc[3], aL[0], aL[1], aL[2], aL[3], bH0, bH1);
    mma_bf16(acc[0], acc[1], acc[2], acc[3], aH[0], aH[1], aH[2], aH[3], bH0, bH1);
}

__device__ __forceinline__ uint32_t smem_u32(const void* p) {
    uint32_t a;
    asm("{ .reg .u64 t; cvta.to.shared.u64 t, %1; cvt.u32.u64 %0, t; }"
        : "=r"(a) : "l"(p));
    return a;
}
__device__ __forceinline__ void cp16(uint32_t dst, const void* src) {
    asm volatile("cp.async.cg.shared.global [%0], [%1], 16;" :: "r"(dst), "l"(src));
}
__device__ __forceinline__ void cp_commit() {
    asm volatile("cp.async.commit_group;" ::: "memory");
}
template <int N>
__device__ __forceinline__ void cp_wait() {
    asm volatile("cp.async.wait_group %0;" :: "n"(N) : "memory");
}
__device__ __forceinline__ void ldsm4(unsigned* r, uint32_t addr) {
    asm volatile("ldmatrix.sync.aligned.m8n8.x4.shared.b16 {%0,%1,%2,%3}, [%4];"
                 : "=r"(r[0]), "=r"(r[1]), "=r"(r[2]), "=r"(r[3]) : "r"(addr));
}

// ---------------------------------------------------------------------------
__global__ void split_kernel(const float* __restrict__ src,
                             __nv_bfloat16* __restrict__ hi,
                             __nv_bfloat16* __restrict__ lo, int n4)
{
    int i = blockIdx.x * blockDim.x + threadIdx.x;
    if (i >= n4) return;
    float4 v = ((const float4*)src)[i];
    unsigned h0, h1, l0, l1;
    split2pack(v.x, v.y, h0, l0);
    split2pack(v.z, v.w, h1, l1);
    ((uint2*)hi)[i] = make_uint2(h0, h1);
    ((uint2*)lo)[i] = make_uint2(l0, l1);
}

// Epilogue write modes
enum { OUT_PLAIN_BIAS = 1, OUT_QKV_HM = 2 };

__device__ __forceinline__ void write_qkv_hm(int m, int n, float2 v)
{
    const int sel = n >> 10;
    const int h   = (n >> 6) & 15;
    const int d   = n & 63;
    const int b   = m >> 12;
    const int ntk = m & 4095;
    float* dst = g_qkv +
        ((((size_t)sel * kB + b) * kH + h) * kN + ntk) * kD + d;
    *(float2*)dst = v;
}

// ---------------------------------------------------------------------------
// bf16x3 GEMM (NT), 3-stage k32 cp.async ring, wait_group<1>, XOR swizzle.
// Block 128x128, 256 thr, warp tile 64x32.
// smem per stage: 4 planes (AH, AL, BH, BL), each 128 rows x 64B (swizzled).
// ---------------------------------------------------------------------------
namespace {
constexpr int ROWB   = 64;               // 32 bf16, no pad; XOR swizzle instead
constexpr int PLANE  = 128 * ROWB;       // 8192 B
constexpr int STAGEB = 4 * PLANE;        // 32768 B
constexpr int NSTAGE = 3;
constexpr int SMEM_GEMM = NSTAGE * STAGEB;   // 98304 B -> 2 CTA/SM
}

template <int OUT_MODE>
__global__ __launch_bounds__(256)
void bf16x3_gemm_cp(const __nv_bfloat16* __restrict__ AH,
                    const __nv_bfloat16* __restrict__ AL,
                    const __nv_bfloat16* __restrict__ BH,
                    const __nv_bfloat16* __restrict__ BL,
                    float* __restrict__ C, const float* __restrict__ bias,
                    int M, int N, int K)
{
    extern __shared__ char sm[];
    const uint32_t sbase = smem_u32(sm);

    const int t = threadIdx.x;
    const int warp = t >> 5, lane = t & 31;
    const int wm = (warp & 1) * 64;
    const int wn = (warp >> 1) * 32;
    const int m0 = blockIdx.y * 128, n0 = blockIdx.x * 128;

    // cp loader: 512 cp16 per plane; each thread does 2: f = t + 256j
    //   row = f>>2 (0..127), chunk c = f&3, swizzled c' = c ^ ((row>>1)&3)
    const int lrowA = t >> 2, lcA = t & 3;
    const int lrowB = (t + 256) >> 2, lcB = (t + 256) & 3;
    const uint32_t dA = lrowA * ROWB + ((lcA ^ ((lrowA >> 1) & 3)) << 4);
    const uint32_t dB = lrowB * ROWB + ((lcB ^ ((lrowB >> 1) & 3)) << 4);

    const __nv_bfloat16* pAH = AH + (size_t)m0 * K;
    const __nv_bfloat16* pAL = AL + (size_t)m0 * K;
    const __nv_bfloat16* pBH = BH + (size_t)n0 * K;
    const __nv_bfloat16* pBL = BL + (size_t)n0 * K;

    auto load_stage = [&](uint32_t stoff, int k0) {
        const uint32_t s0 = sbase + stoff;
        const size_t gA = (size_t)lrowA * K + k0 + lcA * 8;
        const size_t gB = (size_t)lrowB * K + k0 + lcB * 8;
        cp16(s0 + dA,             pAH + gA);
        cp16(s0 + dB,             pAH + gB);
        cp16(s0 + PLANE + dA,     pAL + gA);
        cp16(s0 + PLANE + dB,     pAL + gB);
        cp16(s0 + 2 * PLANE + dA, pBH + gA);
        cp16(s0 + 2 * PLANE + dB, pBH + gB);
        cp16(s0 + 3 * PLANE + dA, pBL + gA);
        cp16(s0 + 3 * PLANE + dB, pBL + gB);
    };

    float acc[4][4][4];
#pragma unroll
    for (int i = 0; i < 4; ++i)
#pragma unroll
        for (int j = 0; j < 4; ++j)
#pragma unroll
            for (int q = 0; q < 4; ++q) acc[i][j][q] = 0.f;

    // LDSM lane geometry + per-lane swizzle keys
    const int quad = lane >> 3;
    const int l8   = lane & 7;
    const int roff = (quad & 1) * 8 + l8;        // row offset within 16-row tile
    const int kq   = quad >> 1;                  // k chunk 0/1 within k32 half
    const int xk   = (roff >> 1) & 3;            // tile bases are mult of 16
    const uint32_t swz0 = (uint32_t)(((0 + kq) ^ xk) << 4);   // s = 0
    const uint32_t swz1 = (uint32_t)(((2 + kq) ^ xk) << 4);   // s = 1

    const int nch = K / 32;              // 32

    load_stage(0 * STAGEB, 0);  cp_commit();
    load_stage(1 * STAGEB, 32); cp_commit();

    for (int ch = 0; ch < nch; ch += 3) {
#pragma unroll
        for (int u = 0; u < 3; ++u) {
            const int cc = ch + u;
            if (cc >= nch) break;

            cp_wait<1>();                 // stage cc ready; cc+1 may be in flight
            __syncthreads();

            if (cc + 2 < nch)
                load_stage((uint32_t)(((u + 2) % 3) * STAGEB), (cc + 2) * 32);
            cp_commit();

            const uint32_t sb = sbase + (uint32_t)(u * STAGEB);
#pragma unroll
            for (int s = 0; s < 2; ++s) {
                const uint32_t swz = s ? swz1 : swz0;
                unsigned aH[4][4], aL[4][4];
#pragma unroll
                for (int mt = 0; mt < 4; ++mt) {
                    const uint32_t ra = sb + (wm + mt * 16 + roff) * ROWB + swz;
                    ldsm4(aH[mt], ra);
                    ldsm4(aL[mt], ra + PLANE);
                }
                unsigned bfH[2][4], bfL[2][4];
#pragma unroll
                for (int pt = 0; pt < 2; ++pt) {
                    const uint32_t rb = sb + 2 * PLANE
                                      + (wn + pt * 16 + roff) * ROWB + swz;
                    ldsm4(bfH[pt], rb);
                    ldsm4(bfL[pt], rb + PLANE);
                }
#pragma unroll
                for (int mt = 0; mt < 4; ++mt)
#pragma unroll
                    for (int nt = 0; nt < 4; ++nt) {
                        const int pt = nt >> 1, hi = nt & 1;
                        mma3(acc[mt][nt], aH[mt], aL[mt],
                             bfH[pt][hi], bfH[pt][2 + hi],
                             bfL[pt][hi], bfL[pt][2 + hi]);
                    }
            }
        }
    }

    const int r = lane >> 2, c = lane & 3;
#pragma unroll
    for (int mt = 0; mt < 4; ++mt) {
#pragma unroll
        for (int nt = 0; nt < 4; ++nt) {
            const int m = m0 + wm + mt * 16 + r;
            const int n = n0 + wn + nt * 8 + c * 2;
            float2 v0 = make_float2(acc[mt][nt][0], acc[mt][nt][1]);
            float2 v1 = make_float2(acc[mt][nt][2], acc[mt][nt][3]);
            if (OUT_MODE == OUT_QKV_HM) {
                write_qkv_hm(m, n, v0);
                write_qkv_hm(m + 8, n, v1);
            } else {
                const float b0v = bias[n], b1v = bias[n + 1];
                v0.x += b0v; v0.y += b1v;
                v1.x += b0v; v1.y += b1v;
                *(float2*)(C + (size_t)m * N + n)       = v0;
                *(float2*)(C + (size_t)(m + 8) * N + n) = v1;
            }
        }
    }
}

// ---------------------------------------------------------------------------
// Logits on tensor cores (R7 winner): partial[split][bh] = K^T Q over split-N.
// ---------------------------------------------------------------------------
__global__ __launch_bounds__(256)
void attn_logits_mma()
{
    __shared__ unsigned AH[32][72], AL[32][72];   // k^T planes
    __shared__ unsigned BH[32][72], BL[32][72];   // q^T planes

    const int t = threadIdx.x;
    const int warp = t >> 5, lane = t & 31;
    const int wm = (warp & 1) * 32;
    const int wn = (warp >> 1) * 16;
    const int r = lane >> 2, c = lane & 3;
    const int split = blockIdx.x, bh = blockIdx.y;

    const float* qb = g_qkv + (size_t)(0 * kB * kH + bh) * kN * kD;
    const float* kb = g_qkv + (size_t)(1 * kB * kH + bh) * kN * kD;

    float acc[2][2][4];
#pragma unroll
    for (int i = 0; i < 2; ++i)
#pragma unroll
        for (int j = 0; j < 2; ++j)
#pragma unroll
            for (int q = 0; q < 4; ++q) acc[i][j][q] = 0.f;

    const int nbeg = split * (kN / kSplits);
    for (int n0 = nbeg; n0 < nbeg + kN / kSplits; n0 += 64) {
#pragma unroll
        for (int i = 0; i < 4; ++i) {
            const int f = t + i * 256;
            const float* src = (f < 512) ? kb : qb;
            unsigned (*pH)[72] = (f < 512) ? AH : BH;
            unsigned (*pL)[72] = (f < 512) ? AL : BL;
            const int g  = f & 511;
            const int pr = g >> 4;
            const int d4 = (g & 15) * 4;
            const float* p0 = src + (size_t)(n0 + 2 * pr) * kD + d4;
            float4 v0 = *(const float4*)p0;
            float4 v1 = *(const float4*)(p0 + kD);
            split2pack(v0.x, v1.x, pH[pr][d4 + 0], pL[pr][d4 + 0]);
            split2pack(v0.y, v1.y, pH[pr][d4 + 1], pL[pr][d4 + 1]);
            split2pack(v0.z, v1.z, pH[pr][d4 + 2], pL[pr][d4 + 2]);
            split2pack(v0.w, v1.w, pH[pr][d4 + 3], pL[pr][d4 + 3]);
        }
        __syncthreads();

#pragma unroll
        for (int s = 0; s < 4; ++s) {
            const int base = 8 * s;
            unsigned aH[2][4], aL[2][4], bH[2][2], bL[2][2];
#pragma unroll
            for (int mt = 0; mt < 2; ++mt) {
                const int mr = wm + mt * 16 + r;
                aH[mt][0] = AH[base + c][mr];     aH[mt][1] = AH[base + c][mr + 8];
                aH[mt][2] = AH[base + c + 4][mr]; aH[mt][3] = AH[base + c + 4][mr + 8];
                aL[mt][0] = AL[base + c][mr];     aL[mt][1] = AL[base + c][mr + 8];
                aL[mt][2] = AL[base + c + 4][mr]; aL[mt][3] = AL[base + c + 4][mr + 8];
            }
#pragma unroll
            for (int nt = 0; nt < 2; ++nt) {
                const int nr = wn + nt * 8 + r;
                bH[nt][0] = BH[base + c][nr]; bH[nt][1] = BH[base + c + 4][nr];
                bL[nt][0] = BL[base + c][nr]; bL[nt][1] = BL[base + c + 4][nr];
            }
#pragma unroll
            for (int mt = 0; mt < 2; ++mt)
#pragma unroll
                for (int nt = 0; nt < 2; ++nt)
                    mma3(acc[mt][nt], aH[mt], aL[mt],
                         bH[nt][0], bH[nt][1], bL[nt][0], bL[nt][1]);
        }
        __syncthreads();
    }

    float* o = g_attn + ((size_t)split * (kB * kH) + bh) * (kD * kD);
#pragma unroll
    for (int mt = 0; mt < 2; ++mt) {
#pragma unroll
        for (int nt = 0; nt < 2; ++nt) {
            const int dr = wm + mt * 16 + r;
            const int e0 = wn + nt * 8 + 2 * c;
            *(float2*)(o + dr * kD + e0)       = make_float2(acc[mt][nt][0], acc[mt][nt][1]);
            *(float2*)(o + (dr + 8) * kD + e0) = make_float2(acc[mt][nt][2], acc[mt][nt][3]);
        }
    }
}

// ---------------------------------------------------------------------------
__global__ void softmax_kernel(const float* __restrict__ alpha)
{
    const int row = blockIdx.x;
    const int t = threadIdx.x;
    const int h = (row >> 6) & 15;
    __shared__ float s[64];

    float v = 0.f;
#pragma unroll
    for (int sp = 0; sp < kSplits; ++sp)
        v += g_attn[(size_t)sp * (kB * kH * kD * kD) + (size_t)row * kD + t];
    v /= alpha[h];

    s[t] = v;
    __syncthreads();
    for (int off = 32; off > 0; off >>= 1) {
        if (t < off) s[t] = fmaxf(s[t], s[t + off]);
        __syncthreads();
    }
    const float mx = s[0];
    __syncthreads();
    const float e = expf(v - mx);
    s[t] = e;
    __syncthreads();
    for (int off = 32; off > 0; off >>= 1) {
        if (t < off) s[t] += s[t + off];
        __syncthreads();
    }
    g_attnP[(size_t)row * kD + t] = e / s[0];
}

// ---------------------------------------------------------------------------
// P @ V^T on tensor cores (R8 winner) — epilogue writes SPLIT bf16 out.
// ---------------------------------------------------------------------------
__global__ __launch_bounds__(256)
void pv_mma()
{
    __shared__ unsigned VH[32][72], VL[32][72];
    __shared__ unsigned PH[32][72], PL[32][72];

    const int t = threadIdx.x;
    const int warp = t >> 5, lane = t & 31;
    const int wm = (warp & 1) * 32;       // token
    const int wn = (warp >> 1) * 16;      // d
    const int r = lane >> 2, c = lane & 3;
    const int tk0 = blockIdx.x * 64;
    const int bh = blockIdx.y;
    const int b = bh >> 4, h = bh & 15;

    const float* Vg = g_qkv + (size_t)(2 * kB * kH + bh) * kN * kD
                    + (size_t)tk0 * kD;
    const float* Pg = g_attnP + (size_t)bh * (kD * kD);

#pragma unroll
    for (int i = 0; i < 4; ++i) {
        const int f = t + i * 256;
        const int row = f >> 4;
        const int e4 = (f & 15) * 4;
        const int kp = e4 >> 1;
        float4 v = *(const float4*)(Vg + (size_t)row * kD + e4);
        split2pack(v.x, v.y, VH[kp][row], VL[kp][row]);
        split2pack(v.z, v.w, VH[kp + 1][row], VL[kp + 1][row]);
        float4 p = *(const float4*)(Pg + row * kD + e4);
        split2pack(p.x, p.y, PH[kp][row], PL[kp][row]);
        split2pack(p.z, p.w, PH[kp + 1][row], PL[kp + 1][row]);
    }
    __syncthreads();

    float acc[2][2][4];
#pragma unroll
    for (int i = 0; i < 2; ++i)
#pragma unroll
        for (int j = 0; j < 2; ++j)
#pragma unroll
            for (int q = 0; q < 4; ++q) acc[i][j][q] = 0.f;

#pragma unroll
    for (int s = 0; s < 4; ++s) {
        const int base = 8 * s;
        unsigned aH[2][4], aL[2][4], bH[2][2], bL[2][2];
#pragma unroll
        for (int mt = 0; mt < 2; ++mt) {
            const int mr = wm + mt * 16 + r;
            aH[mt][0] = VH[base + c][mr];     aH[mt][1] = VH[base + c][mr + 8];
            aH[mt][2] = VH[base + c + 4][mr]; aH[mt][3] = VH[base + c + 4][mr + 8];
            aL[mt][0] = VL[base + c][mr];     aL[mt][1] = VL[base + c][mr + 8];
            aL[mt][2] = VL[base + c + 4][mr]; aL[mt][3] = VL[base + c + 4][mr + 8];
        }
#pragma unroll
        for (int nt = 0; nt < 2; ++nt) {
            const int nr = wn + nt * 8 + r;
            bH[nt][0] = PH[base + c][nr]; bH[nt][1] = PH[base + c + 4][nr];
            bL[nt][0] = PL[base + c][nr]; bL[nt][1] = PL[base + c + 4][nr];
        }
#pragma unroll
        for (int mt = 0; mt < 2; ++mt)
#pragma unroll
            for (int nt = 0; nt < 2; ++nt)
                mma3(acc[mt][nt], aH[mt], aL[mt],
                     bH[nt][0], bH[nt][1], bL[nt][0], bL[nt][1]);
    }

    // epilogue: split out[token][channel] directly into bf16 hi/lo arrays
#pragma unroll
    for (int mt = 0; mt < 2; ++mt) {
#pragma unroll
        for (int nt = 0; nt < 2; ++nt) {
            const int tok = tk0 + wm + mt * 16 + r;
            const int ch = h * kD + wn + nt * 8 + 2 * c;       // even
            const size_t i0 = (((size_t)b * kN + tok) * kC + ch) >> 1;
            const size_t i1 = (((size_t)b * kN + tok + 8) * kC + ch) >> 1;
            unsigned hw, lw;
            split2pack(acc[mt][nt][0], acc[mt][nt][1], hw, lw);
            ((unsigned*)g_outH)[i0] = hw;
            ((unsigned*)g_outL)[i0] = lw;
            split2pack(acc[mt][nt][2], acc[mt][nt][3], hw, lw);
            ((unsigned*)g_outH)[i1] = hw;
            ((unsigned*)g_outL)[i1] = lw;
        }
    }
}

// ---------------------------------------------------------------------------
extern "C" void kernel_launch(void* const* d_in, const int* in_sizes, int n_in,
                              void* d_out, int out_size)
{
    const float* x = nullptr;
    const float* Wqkv = nullptr;
    const float* Wproj = nullptr;
    const float* bproj = nullptr;
    const float* alpha = nullptr;
    for (int i = 0; i < n_in; ++i) {
        switch (in_sizes[i]) {
            case kM * kC:    x     = (const float*)d_in[i]; break;
            case kQKV * kC:  Wqkv  = (const float*)d_in[i]; break;
            case kC * kC:    Wproj = (const float*)d_in[i]; break;
            case kC:         bproj = (const float*)d_in[i]; break;
            case kH:         alpha = (const float*)d_in[i]; break;
            default: break;
        }
    }

    __nv_bfloat16 *xH, *xL, *wqH, *wqL, *wpH, *wpL, *oH, *oL;
    cudaGetSymbolAddress((void**)&xH, g_xH);     cudaGetSymbolAddress((void**)&xL, g_xL);
    cudaGetSymbolAddress((void**)&wqH, g_wqkvH); cudaGetSymbolAddress((void**)&wqL, g_wqkvL);
    cudaGetSymbolAddress((void**)&wpH, g_wprojH); cudaGetSymbolAddress((void**)&wpL, g_wprojL);
    cudaGetSymbolAddress((void**)&oH, g_outH);   cudaGetSymbolAddress((void**)&oL, g_outL);

    cudaFuncSetAttribute(bf16x3_gemm_cp<OUT_QKV_HM>,
                         cudaFuncAttributeMaxDynamicSharedMemorySize, SMEM_GEMM);
    cudaFuncSetAttribute(bf16x3_gemm_cp<OUT_PLAIN_BIAS>,
                         cudaFuncAttributeMaxDynamicSharedMemorySize, SMEM_GEMM);

    // 0) pre-split GEMM operands
    {
        int n4 = kM * kC / 4;
        split_kernel<<<(n4 + 255) / 256, 256>>>(x, xH, xL, n4);
        n4 = kQKV * kC / 4;
        split_kernel<<<(n4 + 255) / 256, 256>>>(Wqkv, wqH, wqL, n4);
        n4 = kC * kC / 4;
        split_kernel<<<(n4 + 255) / 256, 256>>>(Wproj, wpH, wpL, n4);
    }

    // 1) QKV projection -> head-major qkv
    dim3 g1(kQKV / 128, kM / 128);
    bf16x3_gemm_cp<OUT_QKV_HM><<<g1, 256, SMEM_GEMM>>>(
        xH, xL, wqH, wqL, nullptr, nullptr, kM, kQKV, kC);

    // 2) Channel-attention logits on tensor cores
    attn_logits_mma<<<dim3(kSplits, kB * kH), 256>>>();

    // 3) Softmax
    softmax_kernel<<<kB * kH * kD, kD>>>(alpha);

    // 4) P @ V^T on tensor cores (emits split bf16 out)
    pv_mma<<<dim3(kN / 64, kB * kH), 256>>>();

    // 5) Output projection + bias
    dim3 g3(kC / 128, kM / 128);
    bf16x3_gemm_cp<OUT_PLAIN_BIAS><<<g3, 256, SMEM_GEMM>>>(
        oH, oL, wpH, wpL, (float*)d_out, bproj, kM, kC, kC);
}

// round 12
// speedup vs baseline: 1.3301x; 1.0099x over previous
#include <cuda_runtime.h>
#include <cuda_bf16.h>
#include <cstdint>

// ---------------------------------------------------------------------------
// SpectralMSA channel attention — Round 12: product-interleaved HMMA order.
//   R11 pipeline (3-stage k32 cp.async, wait_group<1>, XOR swizzle) but the
//   three bf16x3 products are emitted in passes (HL-all, LH-all, HH-all) so
//   consecutive HMMAs hit different accumulators -> no RAW serialization.
// ---------------------------------------------------------------------------

namespace {
constexpr int kB = 4;
constexpr int kN = 4096;
constexpr int kC = 1024;
constexpr int kH = 16;
constexpr int kD = 64;
constexpr int kM = kB * kN;        // 16384
constexpr int kQKV = 3 * kC;       // 3072
constexpr int kSplits = 8;
}

// fp32 scratch
__device__ float g_qkv[(size_t)3 * kB * kH * kN * kD];   // [sel][b][h][n][d]
__device__ float g_attn[(size_t)kSplits * kB * kH * kD * kD];
__device__ float g_attnP[(size_t)kB * kH * kD * kD];
// split-bf16 operands
__device__ __nv_bfloat16 g_xH[(size_t)kM * kC],      g_xL[(size_t)kM * kC];
__device__ __nv_bfloat16 g_wqkvH[(size_t)kQKV * kC], g_wqkvL[(size_t)kQKV * kC];
__device__ __nv_bfloat16 g_wprojH[(size_t)kC * kC],  g_wprojL[(size_t)kC * kC];
__device__ __nv_bfloat16 g_outH[(size_t)kM * kC],    g_outL[(size_t)kM * kC];

// ---------------- low-level helpers ----------------------------------------
__device__ __forceinline__ void mma_bf16(float& d0, float& d1, float& d2, float& d3,
                                         unsigned a0, unsigned a1, unsigned a2, unsigned a3,
                                         unsigned b0, unsigned b1)
{
    asm volatile(
        "mma.sync.aligned.m16n8k16.row.col.f32.bf16.bf16.f32 "
        "{%0,%1,%2,%3},{%4,%5,%6,%7},{%8,%9},{%0,%1,%2,%3};"
        : "+f"(d0), "+f"(d1), "+f"(d2), "+f"(d3)
        : "r"(a0), "r"(a1), "r"(a2), "r"(a3), "r"(b0), "r"(b1));
}

__device__ __forceinline__ void split2pack(float a, float b, unsigned& h, unsigned& l)
{
    __nv_bfloat16 ha = __float2bfloat16_rn(a), hb = __float2bfloat16_rn(b);
    __nv_bfloat162 ph(ha, hb); h = *(unsigned*)&ph;
    __nv_bfloat162 pl(__float2bfloat16_rn(a - __bfloat162float(ha)),
                      __float2bfloat16_rn(b - __bfloat162float(hb)));
    l = *(unsigned*)&pl;
}

// 3-product accumulate (used by attention kernels, small tiles)
__device__ __forceinline__ void mma3(float* acc,
                                     const unsigned aH[4], const unsigned aL[4],
                                     unsigned bH0, unsigned bH1,
                                     unsigned bL0, unsigned bL1)
{
    mma_bf16(acc[0], acc[1], acc[2], acc[3], aH[0], aH[1], aH[2], aH[3], bL0, bL1);
    mma_bf16(acc[0], acc[1], acc[2], acc[3], aL[0], aL[1], aL[2], aL[3], bH0, bH1);
    mma_bf16(acc[0], acc[1], acc[2], acc[3], aH[0], aH[1], aH[2], aH[3], bH0, bH1);
}

__device__ __forceinline__ uint32_t smem_u32(const void* p) {
    uint32_t a;
    asm("{ .reg .u64 t; cvta.to.shared.u64 t, %1; cvt.u32.u64 %0, t; }"
        : "=r"(a) : "l"(p));
    return a;
}
__device__ __forceinline__ void cp16(uint32_t dst, const void* src) {
    asm volatile("cp.async.cg.shared.global [%0], [%1], 16;" :: "r"(dst), "l"(src));
}
__device__ __forceinline__ void cp_commit() {
    asm volatile("cp.async.commit_group;" ::: "memory");
}
template <int N>
__device__ __forceinline__ void cp_wait() {
    asm volatile("cp.async.wait_group %0;" :: "n"(N) : "memory");
}
__device__ __forceinline__ void ldsm4(unsigned* r, uint32_t addr) {
    asm volatile("ldmatrix.sync.aligned.m8n8.x4.shared.b16 {%0,%1,%2,%3}, [%4];"
                 : "=r"(r[0]), "=r"(r[1]), "=r"(r[2]), "=r"(r[3]) : "r"(addr));
}

// ---------------------------------------------------------------------------
__global__ void split_kernel(const float* __restrict__ src,
                             __nv_bfloat16* __restrict__ hi,
                             __nv_bfloat16* __restrict__ lo, int n4)
{
    int i = blockIdx.x * blockDim.x + threadIdx.x;
    if (i >= n4) return;
    float4 v = ((const float4*)src)[i];
    unsigned h0, h1, l0, l1;
    split2pack(v.x, v.y, h0, l0);
    split2pack(v.z, v.w, h1, l1);
    ((uint2*)hi)[i] = make_uint2(h0, h1);
    ((uint2*)lo)[i] = make_uint2(l0, l1);
}

// Epilogue write modes
enum { OUT_PLAIN_BIAS = 1, OUT_QKV_HM = 2 };

__device__ __forceinline__ void write_qkv_hm(int m, int n, float2 v)
{
    const int sel = n >> 10;
    const int h   = (n >> 6) & 15;
    const int d   = n & 63;
    const int b   = m >> 12;
    const int ntk = m & 4095;
    float* dst = g_qkv +
        ((((size_t)sel * kB + b) * kH + h) * kN + ntk) * kD + d;
    *(float2*)dst = v;
}

// ---------------------------------------------------------------------------
// bf16x3 GEMM (NT), 3-stage k32 cp.async ring, wait_group<1>, XOR swizzle,
// product-interleaved HMMA emission.
// ---------------------------------------------------------------------------
namespace {
constexpr int ROWB   = 64;
constexpr int PLANE  = 128 * ROWB;       // 8192 B
constexpr int STAGEB = 4 * PLANE;        // 32768 B
constexpr int NSTAGE = 3;
constexpr int SMEM_GEMM = NSTAGE * STAGEB;   // 98304 B
}

template <int OUT_MODE>
__global__ __launch_bounds__(256)
void bf16x3_gemm_cp(const __nv_bfloat16* __restrict__ AH,
                    const __nv_bfloat16* __restrict__ AL,
                    const __nv_bfloat16* __restrict__ BH,
                    const __nv_bfloat16* __restrict__ BL,
                    float* __restrict__ C, const float* __restrict__ bias,
                    int M, int N, int K)
{
    extern __shared__ char sm[];
    const uint32_t sbase = smem_u32(sm);

    const int t = threadIdx.x;
    const int warp = t >> 5, lane = t & 31;
    const int wm = (warp & 1) * 64;
    const int wn = (warp >> 1) * 32;
    const int m0 = blockIdx.y * 128, n0 = blockIdx.x * 128;

    const int lrowA = t >> 2, lcA = t & 3;
    const int lrowB = (t + 256) >> 2, lcB = (t + 256) & 3;
    const uint32_t dA = lrowA * ROWB + ((lcA ^ ((lrowA >> 1) & 3)) << 4);
    const uint32_t dB = lrowB * ROWB + ((lcB ^ ((lrowB >> 1) & 3)) << 4);

    const __nv_bfloat16* pAH = AH + (size_t)m0 * K;
    const __nv_bfloat16* pAL = AL + (size_t)m0 * K;
    const __nv_bfloat16* pBH = BH + (size_t)n0 * K;
    const __nv_bfloat16* pBL = BL + (size_t)n0 * K;

    auto load_stage = [&](uint32_t stoff, int k0) {
        const uint32_t s0 = sbase + stoff;
        const size_t gA = (size_t)lrowA * K + k0 + lcA * 8;
        const size_t gB = (size_t)lrowB * K + k0 + lcB * 8;
        cp16(s0 + dA,             pAH + gA);
        cp16(s0 + dB,             pAH + gB);
        cp16(s0 + PLANE + dA,     pAL + gA);
        cp16(s0 + PLANE + dB,     pAL + gB);
        cp16(s0 + 2 * PLANE + dA, pBH + gA);
        cp16(s0 + 2 * PLANE + dB, pBH + gB);
        cp16(s0 + 3 * PLANE + dA, pBL + gA);
        cp16(s0 + 3 * PLANE + dB, pBL + gB);
    };

    float acc[4][4][4];
#pragma unroll
    for (int i = 0; i < 4; ++i)
#pragma unroll
        for (int j = 0; j < 4; ++j)
#pragma unroll
            for (int q = 0; q < 4; ++q) acc[i][j][q] = 0.f;

    const int quad = lane >> 3;
    const int l8   = lane & 7;
    const int roff = (quad & 1) * 8 + l8;
    const int kq   = quad >> 1;
    const int xk   = (roff >> 1) & 3;
    const uint32_t swz0 = (uint32_t)(((0 + kq) ^ xk) << 4);
    const uint32_t swz1 = (uint32_t)(((2 + kq) ^ xk) << 4);

    const int nch = K / 32;

    load_stage(0 * STAGEB, 0);  cp_commit();
    load_stage(1 * STAGEB, 32); cp_commit();

    for (int ch = 0; ch < nch; ch += 3) {
#pragma unroll
        for (int u = 0; u < 3; ++u) {
            const int cc = ch + u;
            if (cc >= nch) break;

            cp_wait<1>();
            __syncthreads();

            if (cc + 2 < nch)
                load_stage((uint32_t)(((u + 2) % 3) * STAGEB), (cc + 2) * 32);
            cp_commit();

            const uint32_t sb = sbase + (uint32_t)(u * STAGEB);
#pragma unroll
            for (int s = 0; s < 2; ++s) {
                const uint32_t swz = s ? swz1 : swz0;
                unsigned aH[4][4], aL[4][4];
#pragma unroll
                for (int mt = 0; mt < 4; ++mt) {
                    const uint32_t ra = sb + (wm + mt * 16 + roff) * ROWB + swz;
                    ldsm4(aH[mt], ra);
                    ldsm4(aL[mt], ra + PLANE);
                }
                unsigned bfH[2][4], bfL[2][4];
#pragma unroll
                for (int pt = 0; pt < 2; ++pt) {
                    const uint32_t rb = sb + 2 * PLANE
                                      + (wn + pt * 16 + roff) * ROWB + swz;
                    ldsm4(bfH[pt], rb);
                    ldsm4(bfL[pt], rb + PLANE);
                }
                // product-interleaved: consecutive HMMAs hit different acc
#pragma unroll
                for (int mt = 0; mt < 4; ++mt)
#pragma unroll
                    for (int nt = 0; nt < 4; ++nt) {
                        const int pt = nt >> 1, hi = nt & 1;
                        mma_bf16(acc[mt][nt][0], acc[mt][nt][1],
                                 acc[mt][nt][2], acc[mt][nt][3],
                                 aH[mt][0], aH[mt][1], aH[mt][2], aH[mt][3],
                                 bfL[pt][hi], bfL[pt][2 + hi]);
                    }
#pragma unroll
                for (int mt = 0; mt < 4; ++mt)
#pragma unroll
                    for (int nt = 0; nt < 4; ++nt) {
                        const int pt = nt >> 1, hi = nt & 1;
                        mma_bf16(acc[mt][nt][0], acc[mt][nt][1],
                                 acc[mt][nt][2], acc[mt][nt][3],
                                 aL[mt][0], aL[mt][1], aL[mt][2], aL[mt][3],
                                 bfH[pt][hi], bfH[pt][2 + hi]);
                    }
#pragma unroll
                for (int mt = 0; mt < 4; ++mt)
#pragma unroll
                    for (int nt = 0; nt < 4; ++nt) {
                        const int pt = nt >> 1, hi = nt & 1;
                        mma_bf16(acc[mt][nt][0], acc[mt][nt][1],
                                 acc[mt][nt][2], acc[mt][nt][3],
                                 aH[mt][0], aH[mt][1], aH[mt][2], aH[mt][3],
                                 bfH[pt][hi], bfH[pt][2 + hi]);
                    }
            }
        }
    }

    const int r = lane >> 2, c = lane & 3;
#pragma unroll
    for (int mt = 0; mt < 4; ++mt) {
#pragma unroll
        for (int nt = 0; nt < 4; ++nt) {
            const int m = m0 + wm + mt * 16 + r;
            const int n = n0 + wn + nt * 8 + c * 2;
            float2 v0 = make_float2(acc[mt][nt][0], acc[mt][nt][1]);
            float2 v1 = make_float2(acc[mt][nt][2], acc[mt][nt][3]);
            if (OUT_MODE == OUT_QKV_HM) {
                write_qkv_hm(m, n, v0);
                write_qkv_hm(m + 8, n, v1);
            } else {
                const float b0v = bias[n], b1v = bias[n + 1];
                v0.x += b0v; v0.y += b1v;
                v1.x += b0v; v1.y += b1v;
                *(float2*)(C + (size_t)m * N + n)       = v0;
                *(float2*)(C + (size_t)(m + 8) * N + n) = v1;
            }
        }
    }
}

// ---------------------------------------------------------------------------
// Logits on tensor cores (R7 winner).
// ---------------------------------------------------------------------------
__global__ __launch_bounds__(256)
void attn_logits_mma()
{
    __shared__ unsigned AH[32][72], AL[32][72];
    __shared__ unsigned BH[32][72], BL[32][72];

    const int t = threadIdx.x;
    const int warp = t >> 5, lane = t & 31;
    const int wm = (warp & 1) * 32;
    const int wn = (warp >> 1) * 16;
    const int r = lane >> 2, c = lane & 3;
    const int split = blockIdx.x, bh = blockIdx.y;

    const float* qb = g_qkv + (size_t)(0 * kB * kH + bh) * kN * kD;
    const float* kb = g_qkv + (size_t)(1 * kB * kH + bh) * kN * kD;

    float acc[2][2][4];
#pragma unroll
    for (int i = 0; i < 2; ++i)
#pragma unroll
        for (int j = 0; j < 2; ++j)
#pragma unroll
            for (int q = 0; q < 4; ++q) acc[i][j][q] = 0.f;

    const int nbeg = split * (kN / kSplits);
    for (int n0 = nbeg; n0 < nbeg + kN / kSplits; n0 += 64) {
#pragma unroll
        for (int i = 0; i < 4; ++i) {
            const int f = t + i * 256;
            const float* src = (f < 512) ? kb : qb;
            unsigned (*pH)[72] = (f < 512) ? AH : BH;
            unsigned (*pL)[72] = (f < 512) ? AL : BL;
            const int g  = f & 511;
            const int pr = g >> 4;
            const int d4 = (g & 15) * 4;
            const float* p0 = src + (size_t)(n0 + 2 * pr) * kD + d4;
            float4 v0 = *(const float4*)p0;
            float4 v1 = *(const float4*)(p0 + kD);
            split2pack(v0.x, v1.x, pH[pr][d4 + 0], pL[pr][d4 + 0]);
            split2pack(v0.y, v1.y, pH[pr][d4 + 1], pL[pr][d4 + 1]);
            split2pack(v0.z, v1.z, pH[pr][d4 + 2], pL[pr][d4 + 2]);
            split2pack(v0.w, v1.w, pH[pr][d4 + 3], pL[pr][d4 + 3]);
        }
        __syncthreads();

#pragma unroll
        for (int s = 0; s < 4; ++s) {
            const int base = 8 * s;
            unsigned aH[2][4], aL[2][4], bH[2][2], bL[2][2];
#pragma unroll
            for (int mt = 0; mt < 2; ++mt) {
                const int mr = wm + mt * 16 + r;
                aH[mt][0] = AH[base + c][mr];     aH[mt][1] = AH[base + c][mr + 8];
                aH[mt][2] = AH[base + c + 4][mr]; aH[mt][3] = AH[base + c + 4][mr + 8];
                aL[mt][0] = AL[base + c][mr];     aL[mt][1] = AL[base + c][mr + 8];
                aL[mt][2] = AL[base + c + 4][mr]; aL[mt][3] = AL[base + c + 4][mr + 8];
            }
#pragma unroll
            for (int nt = 0; nt < 2; ++nt) {
                const int nr = wn + nt * 8 + r;
                bH[nt][0] = BH[base + c][nr]; bH[nt][1] = BH[base + c + 4][nr];
                bL[nt][0] = BL[base + c][nr]; bL[nt][1] = BL[base + c + 4][nr];
            }
#pragma unroll
            for (int mt = 0; mt < 2; ++mt)
#pragma unroll
                for (int nt = 0; nt < 2; ++nt)
                    mma3(acc[mt][nt], aH[mt], aL[mt],
                         bH[nt][0], bH[nt][1], bL[nt][0], bL[nt][1]);
        }
        __syncthreads();
    }

    float* o = g_attn + ((size_t)split * (kB * kH) + bh) * (kD * kD);
#pragma unroll
    for (int mt = 0; mt < 2; ++mt) {
#pragma unroll
        for (int nt = 0; nt < 2; ++nt) {
            const int dr = wm + mt * 16 + r;
            const int e0 = wn + nt * 8 + 2 * c;
            *(float2*)(o + dr * kD + e0)       = make_float2(acc[mt][nt][0], acc[mt][nt][1]);
            *(float2*)(o + (dr + 8) * kD + e0) = make_float2(acc[mt][nt][2], acc[mt][nt][3]);
        }
    }
}

// ---------------------------------------------------------------------------
__global__ void softmax_kernel(const float* __restrict__ alpha)
{
    const int row = blockIdx.x;
    const int t = threadIdx.x;
    const int h = (row >> 6) & 15;
    __shared__ float s[64];

    float v = 0.f;
#pragma unroll
    for (int sp = 0; sp < kSplits; ++sp)
        v += g_attn[(size_t)sp * (kB * kH * kD * kD) + (size_t)row * kD + t];
    v /= alpha[h];

    s[t] = v;
    __syncthreads();
    for (int off = 32; off > 0; off >>= 1) {
        if (t < off) s[t] = fmaxf(s[t], s[t + off]);
        __syncthreads();
    }
    const float mx = s[0];
    __syncthreads();
    const float e = expf(v - mx);
    s[t] = e;
    __syncthreads();
    for (int off = 32; off > 0; off >>= 1) {
        if (t < off) s[t] += s[t + off];
        __syncthreads();
    }
    g_attnP[(size_t)row * kD + t] = e / s[0];
}

// ---------------------------------------------------------------------------
// P @ V^T on tensor cores (R8 winner) — epilogue writes SPLIT bf16 out.
// ---------------------------------------------------------------------------
__global__ __launch_bounds__(256)
void pv_mma()
{
    __shared__ unsigned VH[32][72], VL[32][72];
    __shared__ unsigned PH[32][72], PL[32][72];

    const int t = threadIdx.x;
    const int warp = t >> 5, lane = t & 31;
    const int wm = (warp & 1) * 32;
    const int wn = (warp >> 1) * 16;
    const int r = lane >> 2, c = lane & 3;
    const int tk0 = blockIdx.x * 64;
    const int bh = blockIdx.y;
    const int b = bh >> 4, h = bh & 15;

    const float* Vg = g_qkv + (size_t)(2 * kB * kH + bh) * kN * kD
                    + (size_t)tk0 * kD;
    const float* Pg = g_attnP + (size_t)bh * (kD * kD);

#pragma unroll
    for (int i = 0; i < 4; ++i) {
        const int f = t + i * 256;
        const int row = f >> 4;
        const int e4 = (f & 15) * 4;
        const int kp = e4 >> 1;
        float4 v = *(const float4*)(Vg + (size_t)row * kD + e4);
        split2pack(v.x, v.y, VH[kp][row], VL[kp][row]);
        split2pack(v.z, v.w, VH[kp + 1][row], VL[kp + 1][row]);
        float4 p = *(const float4*)(Pg + row * kD + e4);
        split2pack(p.x, p.y, PH[kp][row], PL[kp][row]);
        split2pack(p.z, p.w, PH[kp + 1][row], PL[kp + 1][row]);
    }
    __syncthreads();

    float acc[2][2][4];
#pragma unroll
    for (int i = 0; i < 2; ++i)
#pragma unroll
        for (int j = 0; j < 2; ++j)
#pragma unroll
            for (int q = 0; q < 4; ++q) acc[i][j][q] = 0.f;

#pragma unroll
    for (int s = 0; s < 4; ++s) {
        const int base = 8 * s;
        unsigned aH[2][4], aL[2][4], bH[2][2], bL[2][2];
#pragma unroll
        for (int mt = 0; mt < 2; ++mt) {
            const int mr = wm + mt * 16 + r;
            aH[mt][0] = VH[base + c][mr];     aH[mt][1] = VH[base + c][mr + 8];
            aH[mt][2] = VH[base + c + 4][mr]; aH[mt][3] = VH[base + c + 4][mr + 8];
            aL[mt][0] = VL[base + c][mr];     aL[mt][1] = VL[base + c][mr + 8];
            aL[mt][2] = VL[base + c + 4][mr]; aL[mt][3] = VL[base + c + 4][mr + 8];
        }
#pragma unroll
        for (int nt = 0; nt < 2; ++nt) {
            const int nr = wn + nt * 8 + r;
            bH[nt][0] = PH[base + c][nr]; bH[nt][1] = PH[base + c + 4][nr];
            bL[nt][0] = PL[base + c][nr]; bL[nt][1] = PL[base + c + 4][nr];
        }
#pragma unroll
        for (int mt = 0; mt < 2; ++mt)
#pragma unroll
            for (int nt = 0; nt < 2; ++nt)
                mma3(acc[mt][nt], aH[mt], aL[mt],
                     bH[nt][0], bH[nt][1], bL[nt][0], bL[nt][1]);
    }

#pragma unroll
    for (int mt = 0; mt < 2; ++mt) {
#pragma unroll
        for (int nt = 0; nt < 2; ++nt) {
            const int tok = tk0 + wm + mt * 16 + r;
            const int ch = h * kD + wn + nt * 8 + 2 * c;
            const size_t i0 = (((size_t)b * kN + tok) * kC + ch) >> 1;
            const size_t i1 = (((size_t)b * kN + tok + 8) * kC + ch) >> 1;
            unsigned hw, lw;
            split2pack(acc[mt][nt][0], acc[mt][nt][1], hw, lw);
            ((unsigned*)g_outH)[i0] = hw;
            ((unsigned*)g_outL)[i0] = lw;
            split2pack(acc[mt][nt][2], acc[mt][nt][3], hw, lw);
            ((unsigned*)g_outH)[i1] = hw;
            ((unsigned*)g_outL)[i1] = lw;
        }
    }
}

// ---------------------------------------------------------------------------
extern "C" void kernel_launch(void* const* d_in, const int* in_sizes, int n_in,
                              void* d_out, int out_size)
{
    const float* x = nullptr;
    const float* Wqkv = nullptr;
    const float* Wproj = nullptr;
    const float* bproj = nullptr;
    const float* alpha = nullptr;
    for (int i = 0; i < n_in; ++i) {
        switch (in_sizes[i]) {
            case kM * kC:    x     = (const float*)d_in[i]; break;
            case kQKV * kC:  Wqkv  = (const float*)d_in[i]; break;
            case kC * kC:    Wproj = (const float*)d_in[i]; break;
            case kC:         bproj = (const float*)d_in[i]; break;
            case kH:         alpha = (const float*)d_in[i]; break;
            default: break;
        }
    }

    __nv_bfloat16 *xH, *xL, *wqH, *wqL, *wpH, *wpL, *oH, *oL;
    cudaGetSymbolAddress((void**)&xH, g_xH);     cudaGetSymbolAddress((void**)&xL, g_xL);
    cudaGetSymbolAddress((void**)&wqH, g_wqkvH); cudaGetSymbolAddress((void**)&wqL, g_wqkvL);
    cudaGetSymbolAddress((void**)&wpH, g_wprojH); cudaGetSymbolAddress((void**)&wpL, g_wprojL);
    cudaGetSymbolAddress((void**)&oH, g_outH);   cudaGetSymbolAddress((void**)&oL, g_outL);

    cudaFuncSetAttribute(bf16x3_gemm_cp<OUT_QKV_HM>,
                         cudaFuncAttributeMaxDynamicSharedMemorySize, SMEM_GEMM);
    cudaFuncSetAttribute(bf16x3_gemm_cp<OUT_PLAIN_BIAS>,
                         cudaFuncAttributeMaxDynamicSharedMemorySize, SMEM_GEMM);

    // 0) pre-split GEMM operands
    {
        int n4 = kM * kC / 4;
        split_kernel<<<(n4 + 255) / 256, 256>>>(x, xH, xL, n4);
        n4 = kQKV * kC / 4;
        split_kernel<<<(n4 + 255) / 256, 256>>>(Wqkv, wqH, wqL, n4);
        n4 = kC * kC / 4;
        split_kernel<<<(n4 + 255) / 256, 256>>>(Wproj, wpH, wpL, n4);
    }

    // 1) QKV projection -> head-major qkv
    dim3 g1(kQKV / 128, kM / 128);
    bf16x3_gemm_cp<OUT_QKV_HM><<<g1, 256, SMEM_GEMM>>>(
        xH, xL, wqH, wqL, nullptr, nullptr, kM, kQKV, kC);

    // 2) Channel-attention logits on tensor cores
    attn_logits_mma<<<dim3(kSplits, kB * kH), 256>>>();

    // 3) Softmax
    softmax_kernel<<<kB * kH * kD, kD>>>(alpha);

    // 4) P @ V^T on tensor cores (emits split bf16 out)
    pv_mma<<<dim3(kN / 64, kB * kH), 256>>>();

    // 5) Output projection + bias
    dim3 g3(kC / 128, kM / 128);
    bf16x3_gemm_cp<OUT_PLAIN_BIAS><<<g3, 256, SMEM_GEMM>>>(
        oH, oL, wpH, wpL, (float*)d_out, bproj, kM, kC, kC);
}

// round 13
// speedup vs baseline: 1.3660x; 1.0270x over previous
#include <cuda_runtime.h>
#include <cuda_bf16.h>
#include <cuda_fp16.h>
#include <cstdint>

// ---------------------------------------------------------------------------
// SpectralMSA channel attention — Round 13: fp16 split GEMMs, corrections in
// fp16-accumulate mma (2x rate on every prior arch), main product fp32-accum.
//   hi = fp16(x), lo = fp16(x - hi). Per k16: HH (f32 acc) + HL,LH (f16 acc).
//   R11/R12 pipeline otherwise unchanged (3-stage k32 cp.async, XOR swizzle).
//   Attention path (logits/pv on bf16x3 mma) unchanged.
// ---------------------------------------------------------------------------

namespace {
constexpr int kB = 4;
constexpr int kN = 4096;
constexpr int kC = 1024;
constexpr int kH = 16;
constexpr int kD = 64;
constexpr int kM = kB * kN;        // 16384
constexpr int kQKV = 3 * kC;       // 3072
constexpr int kSplits = 8;
}

// fp32 scratch
__device__ float g_qkv[(size_t)3 * kB * kH * kN * kD];   // [sel][b][h][n][d]
__device__ float g_attn[(size_t)kSplits * kB * kH * kD * kD];
__device__ float g_attnP[(size_t)kB * kH * kD * kD];
// split-fp16 operands
__device__ __half g_xH[(size_t)kM * kC],      g_xL[(size_t)kM * kC];
__device__ __half g_wqkvH[(size_t)kQKV * kC], g_wqkvL[(size_t)kQKV * kC];
__device__ __half g_wprojH[(size_t)kC * kC],  g_wprojL[(size_t)kC * kC];
__device__ __half g_outH[(size_t)kM * kC],    g_outL[(size_t)kM * kC];

// ---------------- low-level helpers ----------------------------------------
// fp16 inputs, fp32 accumulate
__device__ __forceinline__ void mma_f16_f32(float& d0, float& d1, float& d2, float& d3,
                                            unsigned a0, unsigned a1, unsigned a2, unsigned a3,
                                            unsigned b0, unsigned b1)
{
    asm volatile(
        "mma.sync.aligned.m16n8k16.row.col.f32.f16.f16.f32 "
        "{%0,%1,%2,%3},{%4,%5,%6,%7},{%8,%9},{%0,%1,%2,%3};"
        : "+f"(d0), "+f"(d1), "+f"(d2), "+f"(d3)
        : "r"(a0), "r"(a1), "r"(a2), "r"(a3), "r"(b0), "r"(b1));
}
// fp16 inputs, fp16 accumulate (2 packed f16x2 regs)
__device__ __forceinline__ void mma_f16_f16(unsigned& c0, unsigned& c1,
                                            unsigned a0, unsigned a1, unsigned a2, unsigned a3,
                                            unsigned b0, unsigned b1)
{
    asm volatile(
        "mma.sync.aligned.m16n8k16.row.col.f16.f16.f16.f16 "
        "{%0,%1},{%2,%3,%4,%5},{%6,%7},{%0,%1};"
        : "+r"(c0), "+r"(c1)
        : "r"(a0), "r"(a1), "r"(a2), "r"(a3), "r"(b0), "r"(b1));
}
// bf16 mma for attention path
__device__ __forceinline__ void mma_bf16(float& d0, float& d1, float& d2, float& d3,
                                         unsigned a0, unsigned a1, unsigned a2, unsigned a3,
                                         unsigned b0, unsigned b1)
{
    asm volatile(
        "mma.sync.aligned.m16n8k16.row.col.f32.bf16.bf16.f32 "
        "{%0,%1,%2,%3},{%4,%5,%6,%7},{%8,%9},{%0,%1,%2,%3};"
        : "+f"(d0), "+f"(d1), "+f"(d2), "+f"(d3)
        : "r"(a0), "r"(a1), "r"(a2), "r"(a3), "r"(b0), "r"(b1));
}

// bf16 split (attention path)
__device__ __forceinline__ void split2pack_bf(float a, float b, unsigned& h, unsigned& l)
{
    __nv_bfloat16 ha = __float2bfloat16_rn(a), hb = __float2bfloat16_rn(b);
    __nv_bfloat162 ph(ha, hb); h = *(unsigned*)&ph;
    __nv_bfloat162 pl(__float2bfloat16_rn(a - __bfloat162float(ha)),
                      __float2bfloat16_rn(b - __bfloat162float(hb)));
    l = *(unsigned*)&pl;
}
// fp16 split (GEMM path)
__device__ __forceinline__ void split2pack_h(float a, float b, unsigned& h, unsigned& l)
{
    __half ha = __float2half_rn(a), hb = __float2half_rn(b);
    __half2 ph(ha, hb); h = *(unsigned*)&ph;
    __half2 pl(__float2half_rn(a - __half2float(ha)),
               __float2half_rn(b - __half2float(hb)));
    l = *(unsigned*)&pl;
}

// bf16x3 accumulate (attention kernels)
__device__ __forceinline__ void mma3(float* acc,
                                     const unsigned aH[4], const unsigned aL[4],
                                     unsigned bH0, unsigned bH1,
                                     unsigned bL0, unsigned bL1)
{
    mma_bf16(acc[0], acc[1], acc[2], acc[3], aH[0], aH[1], aH[2], aH[3], bL0, bL1);
    mma_bf16(acc[0], acc[1], acc[2], acc[3], aL[0], aL[1], aL[2], aL[3], bH0, bH1);
    mma_bf16(acc[0], acc[1], acc[2], acc[3], aH[0], aH[1], aH[2], aH[3], bH0, bH1);
}

__device__ __forceinline__ uint32_t smem_u32(const void* p) {
    uint32_t a;
    asm("{ .reg .u64 t; cvta.to.shared.u64 t, %1; cvt.u32.u64 %0, t; }"
        : "=r"(a) : "l"(p));
    return a;
}
__device__ __forceinline__ void cp16(uint32_t dst, const void* src) {
    asm volatile("cp.async.cg.shared.global [%0], [%1], 16;" :: "r"(dst), "l"(src));
}
__device__ __forceinline__ void cp_commit() {
    asm volatile("cp.async.commit_group;" ::: "memory");
}
template <int N>
__device__ __forceinline__ void cp_wait() {
    asm volatile("cp.async.wait_group %0;" :: "n"(N) : "memory");
}
__device__ __forceinline__ void ldsm4(unsigned* r, uint32_t addr) {
    asm volatile("ldmatrix.sync.aligned.m8n8.x4.shared.b16 {%0,%1,%2,%3}, [%4];"
                 : "=r"(r[0]), "=r"(r[1]), "=r"(r[2]), "=r"(r[3]) : "r"(addr));
}

// ---------------------------------------------------------------------------
__global__ void split_kernel(const float* __restrict__ src,
                             __half* __restrict__ hi,
                             __half* __restrict__ lo, int n4)
{
    int i = blockIdx.x * blockDim.x + threadIdx.x;
    if (i >= n4) return;
    float4 v = ((const float4*)src)[i];
    unsigned h0, h1, l0, l1;
    split2pack_h(v.x, v.y, h0, l0);
    split2pack_h(v.z, v.w, h1, l1);
    ((uint2*)hi)[i] = make_uint2(h0, h1);
    ((uint2*)lo)[i] = make_uint2(l0, l1);
}

// Epilogue write modes
enum { OUT_PLAIN_BIAS = 1, OUT_QKV_HM = 2 };

__device__ __forceinline__ void write_qkv_hm(int m, int n, float2 v)
{
    const int sel = n >> 10;
    const int h   = (n >> 6) & 15;
    const int d   = n & 63;
    const int b   = m >> 12;
    const int ntk = m & 4095;
    float* dst = g_qkv +
        ((((size_t)sel * kB + b) * kH + h) * kN + ntk) * kD + d;
    *(float2*)dst = v;
}

// ---------------------------------------------------------------------------
// fp16-split GEMM (NT): 3-stage k32 cp.async ring, wait_group<1>, XOR swizzle.
// Per k16: HH fp32-accum; HL + LH into shared fp16 accumulator (2x-rate path).
// ---------------------------------------------------------------------------
namespace {
constexpr int ROWB   = 64;
constexpr int PLANE  = 128 * ROWB;       // 8192 B
constexpr int STAGEB = 4 * PLANE;        // 32768 B
constexpr int NSTAGE = 3;
constexpr int SMEM_GEMM = NSTAGE * STAGEB;   // 98304 B
}

template <int OUT_MODE>
__global__ __launch_bounds__(256)
void f16x3_gemm_cp(const __half* __restrict__ AH,
                   const __half* __restrict__ AL,
                   const __half* __restrict__ BH,
                   const __half* __restrict__ BL,
                   float* __restrict__ C, const float* __restrict__ bias,
                   int M, int N, int K)
{
    extern __shared__ char sm[];
    const uint32_t sbase = smem_u32(sm);

    const int t = threadIdx.x;
    const int warp = t >> 5, lane = t & 31;
    const int wm = (warp & 1) * 64;
    const int wn = (warp >> 1) * 32;
    const int m0 = blockIdx.y * 128, n0 = blockIdx.x * 128;

    const int lrowA = t >> 2, lcA = t & 3;
    const int lrowB = (t + 256) >> 2, lcB = (t + 256) & 3;
    const uint32_t dA = lrowA * ROWB + ((lcA ^ ((lrowA >> 1) & 3)) << 4);
    const uint32_t dB = lrowB * ROWB + ((lcB ^ ((lrowB >> 1) & 3)) << 4);

    const __half* pAH = AH + (size_t)m0 * K;
    const __half* pAL = AL + (size_t)m0 * K;
    const __half* pBH = BH + (size_t)n0 * K;
    const __half* pBL = BL + (size_t)n0 * K;

    auto load_stage = [&](uint32_t stoff, int k0) {
        const uint32_t s0 = sbase + stoff;
        const size_t gA = (size_t)lrowA * K + k0 + lcA * 8;
        const size_t gB = (size_t)lrowB * K + k0 + lcB * 8;
        cp16(s0 + dA,             pAH + gA);
        cp16(s0 + dB,             pAH + gB);
        cp16(s0 + PLANE + dA,     pAL + gA);
        cp16(s0 + PLANE + dB,     pAL + gB);
        cp16(s0 + 2 * PLANE + dA, pBH + gA);
        cp16(s0 + 2 * PLANE + dB, pBH + gB);
        cp16(s0 + 3 * PLANE + dA, pBL + gA);
        cp16(s0 + 3 * PLANE + dB, pBL + gB);
    };

    float acc[4][4][4];
    unsigned accc[4][4][2];        // fp16 correction accumulators (f16x2 pairs)
#pragma unroll
    for (int i = 0; i < 4; ++i)
#pragma unroll
        for (int j = 0; j < 4; ++j) {
#pragma unroll
            for (int q = 0; q < 4; ++q) acc[i][j][q] = 0.f;
            accc[i][j][0] = 0u; accc[i][j][1] = 0u;
        }

    const int quad = lane >> 3;
    const int l8   = lane & 7;
    const int roff = (quad & 1) * 8 + l8;
    const int kq   = quad >> 1;
    const int xk   = (roff >> 1) & 3;
    const uint32_t swz0 = (uint32_t)(((0 + kq) ^ xk) << 4);
    const uint32_t swz1 = (uint32_t)(((2 + kq) ^ xk) << 4);

    const int nch = K / 32;

    load_stage(0 * STAGEB, 0);  cp_commit();
    load_stage(1 * STAGEB, 32); cp_commit();

    for (int ch = 0; ch < nch; ch += 3) {
#pragma unroll
        for (int u = 0; u < 3; ++u) {
            const int cc = ch + u;
            if (cc >= nch) break;

            cp_wait<1>();
            __syncthreads();

            if (cc + 2 < nch)
                load_stage((uint32_t)(((u + 2) % 3) * STAGEB), (cc + 2) * 32);
            cp_commit();

            const uint32_t sb = sbase + (uint32_t)(u * STAGEB);
#pragma unroll
            for (int s = 0; s < 2; ++s) {
                const uint32_t swz = s ? swz1 : swz0;
                unsigned aH[4][4], aL[4][4];
#pragma unroll
                for (int mt = 0; mt < 4; ++mt) {
                    const uint32_t ra = sb + (wm + mt * 16 + roff) * ROWB + swz;
                    ldsm4(aH[mt], ra);
                    ldsm4(aL[mt], ra + PLANE);
                }
                unsigned bfH[2][4], bfL[2][4];
#pragma unroll
                for (int pt = 0; pt < 2; ++pt) {
                    const uint32_t rb = sb + 2 * PLANE
                                      + (wn + pt * 16 + roff) * ROWB + swz;
                    ldsm4(bfH[pt], rb);
                    ldsm4(bfL[pt], rb + PLANE);
                }
                // HH -> fp32 accum
#pragma unroll
                for (int mt = 0; mt < 4; ++mt)
#pragma unroll
                    for (int nt = 0; nt < 4; ++nt) {
                        const int pt = nt >> 1, hi = nt & 1;
                        mma_f16_f32(acc[mt][nt][0], acc[mt][nt][1],
                                    acc[mt][nt][2], acc[mt][nt][3],
                                    aH[mt][0], aH[mt][1], aH[mt][2], aH[mt][3],
                                    bfH[pt][hi], bfH[pt][2 + hi]);
                    }
                // HL -> fp16 accum
#pragma unroll
                for (int mt = 0; mt < 4; ++mt)
#pragma unroll
                    for (int nt = 0; nt < 4; ++nt) {
                        const int pt = nt >> 1, hi = nt & 1;
                        mma_f16_f16(accc[mt][nt][0], accc[mt][nt][1],
                                    aH[mt][0], aH[mt][1], aH[mt][2], aH[mt][3],
                                    bfL[pt][hi], bfL[pt][2 + hi]);
                    }
                // LH -> fp16 accum
#pragma unroll
                for (int mt = 0; mt < 4; ++mt)
#pragma unroll
                    for (int nt = 0; nt < 4; ++nt) {
                        const int pt = nt >> 1, hi = nt & 1;
                        mma_f16_f16(accc[mt][nt][0], accc[mt][nt][1],
                                    aL[mt][0], aL[mt][1], aL[mt][2], aL[mt][3],
                                    bfH[pt][hi], bfH[pt][2 + hi]);
                    }
            }
        }
    }

    const int r = lane >> 2, c = lane & 3;
#pragma unroll
    for (int mt = 0; mt < 4; ++mt) {
#pragma unroll
        for (int nt = 0; nt < 4; ++nt) {
            const int m = m0 + wm + mt * 16 + r;
            const int n = n0 + wn + nt * 8 + c * 2;
            __half2 c01 = *(__half2*)&accc[mt][nt][0];
            __half2 c23 = *(__half2*)&accc[mt][nt][1];
            float2 v0 = make_float2(acc[mt][nt][0] + __half2float(c01.x),
                                    acc[mt][nt][1] + __half2float(c01.y));
            float2 v1 = make_float2(acc[mt][nt][2] + __half2float(c23.x),
                                    acc[mt][nt][3] + __half2float(c23.y));
            if (OUT_MODE == OUT_QKV_HM) {
                write_qkv_hm(m, n, v0);
                write_qkv_hm(m + 8, n, v1);
            } else {
                const float b0v = bias[n], b1v = bias[n + 1];
                v0.x += b0v; v0.y += b1v;
                v1.x += b0v; v1.y += b1v;
                *(float2*)(C + (size_t)m * N + n)       = v0;
                *(float2*)(C + (size_t)(m + 8) * N + n) = v1;
            }
        }
    }
}

// ---------------------------------------------------------------------------
// Logits on tensor cores (R7 winner, bf16x3) — unchanged.
// ---------------------------------------------------------------------------
__global__ __launch_bounds__(256)
void attn_logits_mma()
{
    __shared__ unsigned AH[32][72], AL[32][72];
    __shared__ unsigned BH[32][72], BL[32][72];

    const int t = threadIdx.x;
    const int warp = t >> 5, lane = t & 31;
    const int wm = (warp & 1) * 32;
    const int wn = (warp >> 1) * 16;
    const int r = lane >> 2, c = lane & 3;
    const int split = blockIdx.x, bh = blockIdx.y;

    const float* qb = g_qkv + (size_t)(0 * kB * kH + bh) * kN * kD;
    const float* kb = g_qkv + (size_t)(1 * kB * kH + bh) * kN * kD;

    float acc[2][2][4];
#pragma unroll
    for (int i = 0; i < 2; ++i)
#pragma unroll
        for (int j = 0; j < 2; ++j)
#pragma unroll
            for (int q = 0; q < 4; ++q) acc[i][j][q] = 0.f;

    const int nbeg = split * (kN / kSplits);
    for (int n0 = nbeg; n0 < nbeg + kN / kSplits; n0 += 64) {
#pragma unroll
        for (int i = 0; i < 4; ++i) {
            const int f = t + i * 256;
            const float* src = (f < 512) ? kb : qb;
            unsigned (*pH)[72] = (f < 512) ? AH : BH;
            unsigned (*pL)[72] = (f < 512) ? AL : BL;
            const int g  = f & 511;
            const int pr = g >> 4;
            const int d4 = (g & 15) * 4;
            const float* p0 = src + (size_t)(n0 + 2 * pr) * kD + d4;
            float4 v0 = *(const float4*)p0;
            float4 v1 = *(const float4*)(p0 + kD);
            split2pack_bf(v0.x, v1.x, pH[pr][d4 + 0], pL[pr][d4 + 0]);
            split2pack_bf(v0.y, v1.y, pH[pr][d4 + 1], pL[pr][d4 + 1]);
            split2pack_bf(v0.z, v1.z, pH[pr][d4 + 2], pL[pr][d4 + 2]);
            split2pack_bf(v0.w, v1.w, pH[pr][d4 + 3], pL[pr][d4 + 3]);
        }
        __syncthreads();

#pragma unroll
        for (int s = 0; s < 4; ++s) {
            const int base = 8 * s;
            unsigned aH[2][4], aL[2][4], bH[2][2], bL[2][2];
#pragma unroll
            for (int mt = 0; mt < 2; ++mt) {
                const int mr = wm + mt * 16 + r;
                aH[mt][0] = AH[base + c][mr];     aH[mt][1] = AH[base + c][mr + 8];
                aH[mt][2] = AH[base + c + 4][mr]; aH[mt][3] = AH[base + c + 4][mr + 8];
                aL[mt][0] = AL[base + c][mr];     aL[mt][1] = AL[base + c][mr + 8];
                aL[mt][2] = AL[base + c + 4][mr]; aL[mt][3] = AL[base + c + 4][mr + 8];
            }
#pragma unroll
            for (int nt = 0; nt < 2; ++nt) {
                const int nr = wn + nt * 8 + r;
                bH[nt][0] = BH[base + c][nr]; bH[nt][1] = BH[base + c + 4][nr];
                bL[nt][0] = BL[base + c][nr]; bL[nt][1] = BL[base + c + 4][nr];
            }
#pragma unroll
            for (int mt = 0; mt < 2; ++mt)
#pragma unroll
                for (int nt = 0; nt < 2; ++nt)
                    mma3(acc[mt][nt], aH[mt], aL[mt],
                         bH[nt][0], bH[nt][1], bL[nt][0], bL[nt][1]);
        }
        __syncthreads();
    }

    float* o = g_attn + ((size_t)split * (kB * kH) + bh) * (kD * kD);
#pragma unroll
    for (int mt = 0; mt < 2; ++mt) {
#pragma unroll
        for (int nt = 0; nt < 2; ++nt) {
            const int dr = wm + mt * 16 + r;
            const int e0 = wn + nt * 8 + 2 * c;
            *(float2*)(o + dr * kD + e0)       = make_float2(acc[mt][nt][0], acc[mt][nt][1]);
            *(float2*)(o + (dr + 8) * kD + e0) = make_float2(acc[mt][nt][2], acc[mt][nt][3]);
        }
    }
}

// ---------------------------------------------------------------------------
__global__ void softmax_kernel(const float* __restrict__ alpha)
{
    const int row = blockIdx.x;
    const int t = threadIdx.x;
    const int h = (row >> 6) & 15;
    __shared__ float s[64];

    float v = 0.f;
#pragma unroll
    for (int sp = 0; sp < kSplits; ++sp)
        v += g_attn[(size_t)sp * (kB * kH * kD * kD) + (size_t)row * kD + t];
    v /= alpha[h];

    s[t] = v;
    __syncthreads();
    for (int off = 32; off > 0; off >>= 1) {
        if (t < off) s[t] = fmaxf(s[t], s[t + off]);
        __syncthreads();
    }
    const float mx = s[0];
    __syncthreads();
    const float e = expf(v - mx);
    s[t] = e;
    __syncthreads();
    for (int off = 32; off > 0; off >>= 1) {
        if (t < off) s[t] += s[t + off];
        __syncthreads();
    }
    g_attnP[(size_t)row * kD + t] = e / s[0];
}

// ---------------------------------------------------------------------------
// P @ V^T on tensor cores — epilogue writes SPLIT fp16 out (for GEMM3).
// ---------------------------------------------------------------------------
__global__ __launch_bounds__(256)
void pv_mma()
{
    __shared__ unsigned VH[32][72], VL[32][72];
    __shared__ unsigned PH[32][72], PL[32][72];

    const int t = threadIdx.x;
    const int warp = t >> 5, lane = t & 31;
    const int wm = (warp & 1) * 32;
    const int wn = (warp >> 1) * 16;
    const int r = lane >> 2, c = lane & 3;
    const int tk0 = blockIdx.x * 64;
    const int bh = blockIdx.y;
    const int b = bh >> 4, h = bh & 15;

    const float* Vg = g_qkv + (size_t)(2 * kB * kH + bh) * kN * kD
                    + (size_t)tk0 * kD;
    const float* Pg = g_attnP + (size_t)bh * (kD * kD);

#pragma unroll
    for (int i = 0; i < 4; ++i) {
        const int f = t + i * 256;
        const int row = f >> 4;
        const int e4 = (f & 15) * 4;
        const int kp = e4 >> 1;
        float4 v = *(const float4*)(Vg + (size_t)row * kD + e4);
        split2pack_bf(v.x, v.y, VH[kp][row], VL[kp][row]);
        split2pack_bf(v.z, v.w, VH[kp + 1][row], VL[kp + 1][row]);
        float4 p = *(const float4*)(Pg + row * kD + e4);
        split2pack_bf(p.x, p.y, PH[kp][row], PL[kp][row]);
        split2pack_bf(p.z, p.w, PH[kp + 1][row], PL[kp + 1][row]);
    }
    __syncthreads();

    float acc[2][2][4];
#pragma unroll
    for (int i = 0; i < 2; ++i)
#pragma unroll
        for (int j = 0; j < 2; ++j)
#pragma unroll
            for (int q = 0; q < 4; ++q) acc[i][j][q] = 0.f;

#pragma unroll
    for (int s = 0; s < 4; ++s) {
        const int base = 8 * s;
        unsigned aH[2][4], aL[2][4], bH[2][2], bL[2][2];
#pragma unroll
        for (int mt = 0; mt < 2; ++mt) {
            const int mr = wm + mt * 16 + r;
            aH[mt][0] = VH[base + c][mr];     aH[mt][1] = VH[base + c][mr + 8];
            aH[mt][2] = VH[base + c + 4][mr]; aH[mt][3] = VH[base + c + 4][mr + 8];
            aL[mt][0] = VL[base + c][mr];     aL[mt][1] = VL[base + c][mr + 8];
            aL[mt][2] = VL[base + c + 4][mr]; aL[mt][3] = VL[base + c + 4][mr + 8];
        }
#pragma unroll
        for (int nt = 0; nt < 2; ++nt) {
            const int nr = wn + nt * 8 + r;
            bH[nt][0] = PH[base + c][nr]; bH[nt][1] = PH[base + c + 4][nr];
            bL[nt][0] = PL[base + c][nr]; bL[nt][1] = PL[base + c + 4][nr];
        }
#pragma unroll
        for (int mt = 0; mt < 2; ++mt)
#pragma unroll
            for (int nt = 0; nt < 2; ++nt)
                mma3(acc[mt][nt], aH[mt], aL[mt],
                     bH[nt][0], bH[nt][1], bL[nt][0], bL[nt][1]);
    }

#pragma unroll
    for (int mt = 0; mt < 2; ++mt) {
#pragma unroll
        for (int nt = 0; nt < 2; ++nt) {
            const int tok = tk0 + wm + mt * 16 + r;
            const int ch = h * kD + wn + nt * 8 + 2 * c;
            const size_t i0 = (((size_t)b * kN + tok) * kC + ch) >> 1;
            const size_t i1 = (((size_t)b * kN + tok + 8) * kC + ch) >> 1;
            unsigned hw, lw;
            split2pack_h(acc[mt][nt][0], acc[mt][nt][1], hw, lw);
            ((unsigned*)g_outH)[i0] = hw;
            ((unsigned*)g_outL)[i0] = lw;
            split2pack_h(acc[mt][nt][2], acc[mt][nt][3], hw, lw);
            ((unsigned*)g_outH)[i1] = hw;
            ((unsigned*)g_outL)[i1] = lw;
        }
    }
}

// ---------------------------------------------------------------------------
extern "C" void kernel_launch(void* const* d_in, const int* in_sizes, int n_in,
                              void* d_out, int out_size)
{
    const float* x = nullptr;
    const float* Wqkv = nullptr;
    const float* Wproj = nullptr;
    const float* bproj = nullptr;
    const float* alpha = nullptr;
    for (int i = 0; i < n_in; ++i) {
        switch (in_sizes[i]) {
            case kM * kC:    x     = (const float*)d_in[i]; break;
            case kQKV * kC:  Wqkv  = (const float*)d_in[i]; break;
            case kC * kC:    Wproj = (const float*)d_in[i]; break;
            case kC:         bproj = (const float*)d_in[i]; break;
            case kH:         alpha = (const float*)d_in[i]; break;
            default: break;
        }
    }

    __half *xH, *xL, *wqH, *wqL, *wpH, *wpL, *oH, *oL;
    cudaGetSymbolAddress((void**)&xH, g_xH);     cudaGetSymbolAddress((void**)&xL, g_xL);
    cudaGetSymbolAddress((void**)&wqH, g_wqkvH); cudaGetSymbolAddress((void**)&wqL, g_wqkvL);
    cudaGetSymbolAddress((void**)&wpH, g_wprojH); cudaGetSymbolAddress((void**)&wpL, g_wprojL);
    cudaGetSymbolAddress((void**)&oH, g_outH);   cudaGetSymbolAddress((void**)&oL, g_outL);

    cudaFuncSetAttribute(f16x3_gemm_cp<OUT_QKV_HM>,
                         cudaFuncAttributeMaxDynamicSharedMemorySize, SMEM_GEMM);
    cudaFuncSetAttribute(f16x3_gemm_cp<OUT_PLAIN_BIAS>,
                         cudaFuncAttributeMaxDynamicSharedMemorySize, SMEM_GEMM);

    // 0) pre-split GEMM operands (fp16 hi/lo)
    {
        int n4 = kM * kC / 4;
        split_kernel<<<(n4 + 255) / 256, 256>>>(x, xH, xL, n4);
        n4 = kQKV * kC / 4;
        split_kernel<<<(n4 + 255) / 256, 256>>>(Wqkv, wqH, wqL, n4);
        n4 = kC * kC / 4;
        split_kernel<<<(n4 + 255) / 256, 256>>>(Wproj, wpH, wpL, n4);
    }

    // 1) QKV projection -> head-major qkv
    dim3 g1(kQKV / 128, kM / 128);
    f16x3_gemm_cp<OUT_QKV_HM><<<g1, 256, SMEM_GEMM>>>(
        xH, xL, wqH, wqL, nullptr, nullptr, kM, kQKV, kC);

    // 2) Channel-attention logits on tensor cores
    attn_logits_mma<<<dim3(kSplits, kB * kH), 256>>>();

    // 3) Softmax
    softmax_kernel<<<kB * kH * kD, kD>>>(alpha);

    // 4) P @ V^T on tensor cores (emits split fp16 out)
    pv_mma<<<dim3(kN / 64, kB * kH), 256>>>();

    // 5) Output projection + bias
    dim3 g3(kC / 128, kM / 128);
    f16x3_gemm_cp<OUT_PLAIN_BIAS><<<g3, 256, SMEM_GEMM>>>(
        oH, oL, wpH, wpL, (float*)d_out, bproj, kM, kC, kC);
}

// round 14
// speedup vs baseline: 1.5260x; 1.1171x over previous
#include <cuda_runtime.h>
#include <cuda_bf16.h>
#include <cuda_fp16.h>
#include <cstdint>

// ---------------------------------------------------------------------------
// SpectralMSA channel attention — Round 14: selective 2-term fp16 split.
//   q,k (feed softmax): full 3-term (HH f32-acc + HL,LH f16-acc).
//   v and GEMM3 (linear error paths): 2-term (HH + HL), LH dropped
//   -> 11% fewer HMMA in GEMM1, 33% fewer in GEMM3.
//   Pipeline = R11 (3-stage k32 cp.async, wait_group<1>, XOR swizzle).
// ---------------------------------------------------------------------------

namespace {
constexpr int kB = 4;
constexpr int kN = 4096;
constexpr int kC = 1024;
constexpr int kH = 16;
constexpr int kD = 64;
constexpr int kM = kB * kN;        // 16384
constexpr int kQKV = 3 * kC;       // 3072
constexpr int kSplits = 8;
}

// fp32 scratch
__device__ float g_qkv[(size_t)3 * kB * kH * kN * kD];   // [sel][b][h][n][d]
__device__ float g_attn[(size_t)kSplits * kB * kH * kD * kD];
__device__ float g_attnP[(size_t)kB * kH * kD * kD];
// split-fp16 operands
__device__ __half g_xH[(size_t)kM * kC],      g_xL[(size_t)kM * kC];
__device__ __half g_wqkvH[(size_t)kQKV * kC], g_wqkvL[(size_t)kQKV * kC];
__device__ __half g_wprojH[(size_t)kC * kC],  g_wprojL[(size_t)kC * kC];
__device__ __half g_outH[(size_t)kM * kC],    g_outL[(size_t)kM * kC];

// ---------------- low-level helpers ----------------------------------------
__device__ __forceinline__ void mma_f16_f32(float& d0, float& d1, float& d2, float& d3,
                                            unsigned a0, unsigned a1, unsigned a2, unsigned a3,
                                            unsigned b0, unsigned b1)
{
    asm volatile(
        "mma.sync.aligned.m16n8k16.row.col.f32.f16.f16.f32 "
        "{%0,%1,%2,%3},{%4,%5,%6,%7},{%8,%9},{%0,%1,%2,%3};"
        : "+f"(d0), "+f"(d1), "+f"(d2), "+f"(d3)
        : "r"(a0), "r"(a1), "r"(a2), "r"(a3), "r"(b0), "r"(b1));
}
__device__ __forceinline__ void mma_f16_f16(unsigned& c0, unsigned& c1,
                                            unsigned a0, unsigned a1, unsigned a2, unsigned a3,
                                            unsigned b0, unsigned b1)
{
    asm volatile(
        "mma.sync.aligned.m16n8k16.row.col.f16.f16.f16.f16 "
        "{%0,%1},{%2,%3,%4,%5},{%6,%7},{%0,%1};"
        : "+r"(c0), "+r"(c1)
        : "r"(a0), "r"(a1), "r"(a2), "r"(a3), "r"(b0), "r"(b1));
}
__device__ __forceinline__ void mma_bf16(float& d0, float& d1, float& d2, float& d3,
                                         unsigned a0, unsigned a1, unsigned a2, unsigned a3,
                                         unsigned b0, unsigned b1)
{
    asm volatile(
        "mma.sync.aligned.m16n8k16.row.col.f32.bf16.bf16.f32 "
        "{%0,%1,%2,%3},{%4,%5,%6,%7},{%8,%9},{%0,%1,%2,%3};"
        : "+f"(d0), "+f"(d1), "+f"(d2), "+f"(d3)
        : "r"(a0), "r"(a1), "r"(a2), "r"(a3), "r"(b0), "r"(b1));
}

__device__ __forceinline__ void split2pack_bf(float a, float b, unsigned& h, unsigned& l)
{
    __nv_bfloat16 ha = __float2bfloat16_rn(a), hb = __float2bfloat16_rn(b);
    __nv_bfloat162 ph(ha, hb); h = *(unsigned*)&ph;
    __nv_bfloat162 pl(__float2bfloat16_rn(a - __bfloat162float(ha)),
                      __float2bfloat16_rn(b - __bfloat162float(hb)));
    l = *(unsigned*)&pl;
}
__device__ __forceinline__ void split2pack_h(float a, float b, unsigned& h, unsigned& l)
{
    __half ha = __float2half_rn(a), hb = __float2half_rn(b);
    __half2 ph(ha, hb); h = *(unsigned*)&ph;
    __half2 pl(__float2half_rn(a - __half2float(ha)),
               __float2half_rn(b - __half2float(hb)));
    l = *(unsigned*)&pl;
}

__device__ __forceinline__ void mma3(float* acc,
                                     const unsigned aH[4], const unsigned aL[4],
                                     unsigned bH0, unsigned bH1,
                                     unsigned bL0, unsigned bL1)
{
    mma_bf16(acc[0], acc[1], acc[2], acc[3], aH[0], aH[1], aH[2], aH[3], bL0, bL1);
    mma_bf16(acc[0], acc[1], acc[2], acc[3], aL[0], aL[1], aL[2], aL[3], bH0, bH1);
    mma_bf16(acc[0], acc[1], acc[2], acc[3], aH[0], aH[1], aH[2], aH[3], bH0, bH1);
}

__device__ __forceinline__ uint32_t smem_u32(const void* p) {
    uint32_t a;
    asm("{ .reg .u64 t; cvta.to.shared.u64 t, %1; cvt.u32.u64 %0, t; }"
        : "=r"(a) : "l"(p));
    return a;
}
__device__ __forceinline__ void cp16(uint32_t dst, const void* src) {
    asm volatile("cp.async.cg.shared.global [%0], [%1], 16;" :: "r"(dst), "l"(src));
}
__device__ __forceinline__ void cp_commit() {
    asm volatile("cp.async.commit_group;" ::: "memory");
}
template <int N>
__device__ __forceinline__ void cp_wait() {
    asm volatile("cp.async.wait_group %0;" :: "n"(N) : "memory");
}
__device__ __forceinline__ void ldsm4(unsigned* r, uint32_t addr) {
    asm volatile("ldmatrix.sync.aligned.m8n8.x4.shared.b16 {%0,%1,%2,%3}, [%4];"
                 : "=r"(r[0]), "=r"(r[1]), "=r"(r[2]), "=r"(r[3]) : "r"(addr));
}

// ---------------------------------------------------------------------------
__global__ void split_kernel(const float* __restrict__ src,
                             __half* __restrict__ hi,
                             __half* __restrict__ lo, int n4)
{
    int i = blockIdx.x * blockDim.x + threadIdx.x;
    if (i >= n4) return;
    float4 v = ((const float4*)src)[i];
    unsigned h0, h1, l0, l1;
    split2pack_h(v.x, v.y, h0, l0);
    split2pack_h(v.z, v.w, h1, l1);
    ((uint2*)hi)[i] = make_uint2(h0, h1);
    ((uint2*)lo)[i] = make_uint2(l0, l1);
}

// Epilogue write modes
enum { OUT_PLAIN_BIAS = 1, OUT_QKV_HM = 2 };

__device__ __forceinline__ void write_qkv_hm(int m, int n, float2 v)
{
    const int sel = n >> 10;
    const int h   = (n >> 6) & 15;
    const int d   = n & 63;
    const int b   = m >> 12;
    const int ntk = m & 4095;
    float* dst = g_qkv +
        ((((size_t)sel * kB + b) * kH + h) * kN + ntk) * kD + d;
    *(float2*)dst = v;
}

// ---------------------------------------------------------------------------
// fp16-split GEMM (NT): 3-stage k32 cp.async ring, wait_group<1>, XOR swizzle.
// 3-term (HH + HL + LH) for q,k blocks; 2-term (HH + HL) for v and GEMM3.
// ---------------------------------------------------------------------------
namespace {
constexpr int ROWB   = 64;
constexpr int PLANE  = 128 * ROWB;       // 8192 B
constexpr int STAGEB = 4 * PLANE;        // 32768 B
constexpr int NSTAGE = 3;
constexpr int SMEM_GEMM = NSTAGE * STAGEB;   // 98304 B
}

template <int OUT_MODE>
__global__ __launch_bounds__(256)
void f16x3_gemm_cp(const __half* __restrict__ AH,
                   const __half* __restrict__ AL,
                   const __half* __restrict__ BH,
                   const __half* __restrict__ BL,
                   float* __restrict__ C, const float* __restrict__ bias,
                   int M, int N, int K)
{
    extern __shared__ char sm[];
    const uint32_t sbase = smem_u32(sm);

    const int t = threadIdx.x;
    const int warp = t >> 5, lane = t & 31;
    const int wm = (warp & 1) * 64;
    const int wn = (warp >> 1) * 32;
    const int m0 = blockIdx.y * 128, n0 = blockIdx.x * 128;

    // LH term only where errors pass through softmax (q,k columns of GEMM1)
    const bool use_lh = (OUT_MODE == OUT_QKV_HM) && (n0 < 2 * kC);

    const int lrowA = t >> 2, lcA = t & 3;
    const int lrowB = (t + 256) >> 2, lcB = (t + 256) & 3;
    const uint32_t dA = lrowA * ROWB + ((lcA ^ ((lrowA >> 1) & 3)) << 4);
    const uint32_t dB = lrowB * ROWB + ((lcB ^ ((lrowB >> 1) & 3)) << 4);

    const __half* pAH = AH + (size_t)m0 * K;
    const __half* pAL = AL + (size_t)m0 * K;
    const __half* pBH = BH + (size_t)n0 * K;
    const __half* pBL = BL + (size_t)n0 * K;

    auto load_stage = [&](uint32_t stoff, int k0) {
        const uint32_t s0 = sbase + stoff;
        const size_t gA = (size_t)lrowA * K + k0 + lcA * 8;
        const size_t gB = (size_t)lrowB * K + k0 + lcB * 8;
        cp16(s0 + dA,             pAH + gA);
        cp16(s0 + dB,             pAH + gB);
        if (use_lh) {
            cp16(s0 + PLANE + dA, pAL + gA);
            cp16(s0 + PLANE + dB, pAL + gB);
        }
        cp16(s0 + 2 * PLANE + dA, pBH + gA);
        cp16(s0 + 2 * PLANE + dB, pBH + gB);
        cp16(s0 + 3 * PLANE + dA, pBL + gA);
        cp16(s0 + 3 * PLANE + dB, pBL + gB);
    };

    float acc[4][4][4];
    unsigned accc[4][4][2];        // fp16 correction accumulators
#pragma unroll
    for (int i = 0; i < 4; ++i)
#pragma unroll
        for (int j = 0; j < 4; ++j) {
#pragma unroll
            for (int q = 0; q < 4; ++q) acc[i][j][q] = 0.f;
            accc[i][j][0] = 0u; accc[i][j][1] = 0u;
        }

    const int quad = lane >> 3;
    const int l8   = lane & 7;
    const int roff = (quad & 1) * 8 + l8;
    const int kq   = quad >> 1;
    const int xk   = (roff >> 1) & 3;
    const uint32_t swz0 = (uint32_t)(((0 + kq) ^ xk) << 4);
    const uint32_t swz1 = (uint32_t)(((2 + kq) ^ xk) << 4);

    const int nch = K / 32;

    load_stage(0 * STAGEB, 0);  cp_commit();
    load_stage(1 * STAGEB, 32); cp_commit();

    for (int ch = 0; ch < nch; ch += 3) {
#pragma unroll
        for (int u = 0; u < 3; ++u) {
            const int cc = ch + u;
            if (cc >= nch) break;

            cp_wait<1>();
            __syncthreads();

            if (cc + 2 < nch)
                load_stage((uint32_t)(((u + 2) % 3) * STAGEB), (cc + 2) * 32);
            cp_commit();

            const uint32_t sb = sbase + (uint32_t)(u * STAGEB);
#pragma unroll
            for (int s = 0; s < 2; ++s) {
                const uint32_t swz = s ? swz1 : swz0;
                unsigned aH[4][4], aL[4][4];
#pragma unroll
                for (int mt = 0; mt < 4; ++mt) {
                    const uint32_t ra = sb + (wm + mt * 16 + roff) * ROWB + swz;
                    ldsm4(aH[mt], ra);
                    if (use_lh) ldsm4(aL[mt], ra + PLANE);
                }
                unsigned bfH[2][4], bfL[2][4];
#pragma unroll
                for (int pt = 0; pt < 2; ++pt) {
                    const uint32_t rb = sb + 2 * PLANE
                                      + (wn + pt * 16 + roff) * ROWB + swz;
                    ldsm4(bfH[pt], rb);
                    ldsm4(bfL[pt], rb + PLANE);
                }
                // HH -> fp32 accum
#pragma unroll
                for (int mt = 0; mt < 4; ++mt)
#pragma unroll
                    for (int nt = 0; nt < 4; ++nt) {
                        const int pt = nt >> 1, hi = nt & 1;
                        mma_f16_f32(acc[mt][nt][0], acc[mt][nt][1],
                                    acc[mt][nt][2], acc[mt][nt][3],
                                    aH[mt][0], aH[mt][1], aH[mt][2], aH[mt][3],
                                    bfH[pt][hi], bfH[pt][2 + hi]);
                    }
                // HL -> fp16 accum
#pragma unroll
                for (int mt = 0; mt < 4; ++mt)
#pragma unroll
                    for (int nt = 0; nt < 4; ++nt) {
                        const int pt = nt >> 1, hi = nt & 1;
                        mma_f16_f16(accc[mt][nt][0], accc[mt][nt][1],
                                    aH[mt][0], aH[mt][1], aH[mt][2], aH[mt][3],
                                    bfL[pt][hi], bfL[pt][2 + hi]);
                    }
                // LH -> fp16 accum (q,k blocks only)
                if (use_lh) {
#pragma unroll
                    for (int mt = 0; mt < 4; ++mt)
#pragma unroll
                        for (int nt = 0; nt < 4; ++nt) {
                            const int pt = nt >> 1, hi = nt & 1;
                            mma_f16_f16(accc[mt][nt][0], accc[mt][nt][1],
                                        aL[mt][0], aL[mt][1], aL[mt][2], aL[mt][3],
                                        bfH[pt][hi], bfH[pt][2 + hi]);
                        }
                }
            }
        }
    }

    const int r = lane >> 2, c = lane & 3;
#pragma unroll
    for (int mt = 0; mt < 4; ++mt) {
#pragma unroll
        for (int nt = 0; nt < 4; ++nt) {
            const int m = m0 + wm + mt * 16 + r;
            const int n = n0 + wn + nt * 8 + c * 2;
            __half2 c01 = *(__half2*)&accc[mt][nt][0];
            __half2 c23 = *(__half2*)&accc[mt][nt][1];
            float2 v0 = make_float2(acc[mt][nt][0] + __half2float(c01.x),
                                    acc[mt][nt][1] + __half2float(c01.y));
            float2 v1 = make_float2(acc[mt][nt][2] + __half2float(c23.x),
                                    acc[mt][nt][3] + __half2float(c23.y));
            if (OUT_MODE == OUT_QKV_HM) {
                write_qkv_hm(m, n, v0);
                write_qkv_hm(m + 8, n, v1);
            } else {
                const float b0v = bias[n], b1v = bias[n + 1];
                v0.x += b0v; v0.y += b1v;
                v1.x += b0v; v1.y += b1v;
                *(float2*)(C + (size_t)m * N + n)       = v0;
                *(float2*)(C + (size_t)(m + 8) * N + n) = v1;
            }
        }
    }
}

// ---------------------------------------------------------------------------
// Logits on tensor cores (bf16x3, R7 winner) — unchanged.
// ---------------------------------------------------------------------------
__global__ __launch_bounds__(256)
void attn_logits_mma()
{
    __shared__ unsigned AH[32][72], AL[32][72];
    __shared__ unsigned BH[32][72], BL[32][72];

    const int t = threadIdx.x;
    const int warp = t >> 5, lane = t & 31;
    const int wm = (warp & 1) * 32;
    const int wn = (warp >> 1) * 16;
    const int r = lane >> 2, c = lane & 3;
    const int split = blockIdx.x, bh = blockIdx.y;

    const float* qb = g_qkv + (size_t)(0 * kB * kH + bh) * kN * kD;
    const float* kb = g_qkv + (size_t)(1 * kB * kH + bh) * kN * kD;

    float acc[2][2][4];
#pragma unroll
    for (int i = 0; i < 2; ++i)
#pragma unroll
        for (int j = 0; j < 2; ++j)
#pragma unroll
            for (int q = 0; q < 4; ++q) acc[i][j][q] = 0.f;

    const int nbeg = split * (kN / kSplits);
    for (int n0 = nbeg; n0 < nbeg + kN / kSplits; n0 += 64) {
#pragma unroll
        for (int i = 0; i < 4; ++i) {
            const int f = t + i * 256;
            const float* src = (f < 512) ? kb : qb;
            unsigned (*pH)[72] = (f < 512) ? AH : BH;
            unsigned (*pL)[72] = (f < 512) ? AL : BL;
            const int g  = f & 511;
            const int pr = g >> 4;
            const int d4 = (g & 15) * 4;
            const float* p0 = src + (size_t)(n0 + 2 * pr) * kD + d4;
            float4 v0 = *(const float4*)p0;
            float4 v1 = *(const float4*)(p0 + kD);
            split2pack_bf(v0.x, v1.x, pH[pr][d4 + 0], pL[pr][d4 + 0]);
            split2pack_bf(v0.y, v1.y, pH[pr][d4 + 1], pL[pr][d4 + 1]);
            split2pack_bf(v0.z, v1.z, pH[pr][d4 + 2], pL[pr][d4 + 2]);
            split2pack_bf(v0.w, v1.w, pH[pr][d4 + 3], pL[pr][d4 + 3]);
        }
        __syncthreads();

#pragma unroll
        for (int s = 0; s < 4; ++s) {
            const int base = 8 * s;
            unsigned aH[2][4], aL[2][4], bH[2][2], bL[2][2];
#pragma unroll
            for (int mt = 0; mt < 2; ++mt) {
                const int mr = wm + mt * 16 + r;
                aH[mt][0] = AH[base + c][mr];     aH[mt][1] = AH[base + c][mr + 8];
                aH[mt][2] = AH[base + c + 4][mr]; aH[mt][3] = AH[base + c + 4][mr + 8];
                aL[mt][0] = AL[base + c][mr];     aL[mt][1] = AL[base + c][mr + 8];
                aL[mt][2] = AL[base + c + 4][mr]; aL[mt][3] = AL[base + c + 4][mr + 8];
            }
#pragma unroll
            for (int nt = 0; nt < 2; ++nt) {
                const int nr = wn + nt * 8 + r;
                bH[nt][0] = BH[base + c][nr]; bH[nt][1] = BH[base + c + 4][nr];
                bL[nt][0] = BL[base + c][nr]; bL[nt][1] = BL[base + c + 4][nr];
            }
#pragma unroll
            for (int mt = 0; mt < 2; ++mt)
#pragma unroll
                for (int nt = 0; nt < 2; ++nt)
                    mma3(acc[mt][nt], aH[mt], aL[mt],
                         bH[nt][0], bH[nt][1], bL[nt][0], bL[nt][1]);
        }
        __syncthreads();
    }

    float* o = g_attn + ((size_t)split * (kB * kH) + bh) * (kD * kD);
#pragma unroll
    for (int mt = 0; mt < 2; ++mt) {
#pragma unroll
        for (int nt = 0; nt < 2; ++nt) {
            const int dr = wm + mt * 16 + r;
            const int e0 = wn + nt * 8 + 2 * c;
            *(float2*)(o + dr * kD + e0)       = make_float2(acc[mt][nt][0], acc[mt][nt][1]);
            *(float2*)(o + (dr + 8) * kD + e0) = make_float2(acc[mt][nt][2], acc[mt][nt][3]);
        }
    }
}

// ---------------------------------------------------------------------------
__global__ void softmax_kernel(const float* __restrict__ alpha)
{
    const int row = blockIdx.x;
    const int t = threadIdx.x;
    const int h = (row >> 6) & 15;
    __shared__ float s[64];

    float v = 0.f;
#pragma unroll
    for (int sp = 0; sp < kSplits; ++sp)
        v += g_attn[(size_t)sp * (kB * kH * kD * kD) + (size_t)row * kD + t];
    v /= alpha[h];

    s[t] = v;
    __syncthreads();
    for (int off = 32; off > 0; off >>= 1) {
        if (t < off) s[t] = fmaxf(s[t], s[t + off]);
        __syncthreads();
    }
    const float mx = s[0];
    __syncthreads();
    const float e = expf(v - mx);
    s[t] = e;
    __syncthreads();
    for (int off = 32; off > 0; off >>= 1) {
        if (t < off) s[t] += s[t + off];
        __syncthreads();
    }
    g_attnP[(size_t)row * kD + t] = e / s[0];
}

// ---------------------------------------------------------------------------
// P @ V^T on tensor cores — epilogue writes SPLIT fp16 out (for GEMM3).
// ---------------------------------------------------------------------------
__global__ __launch_bounds__(256)
void pv_mma()
{
    __shared__ unsigned VH[32][72], VL[32][72];
    __shared__ unsigned PH[32][72], PL[32][72];

    const int t = threadIdx.x;
    const int warp = t >> 5, lane = t & 31;
    const int wm = (warp & 1) * 32;
    const int wn = (warp >> 1) * 16;
    const int r = lane >> 2, c = lane & 3;
    const int tk0 = blockIdx.x * 64;
    const int bh = blockIdx.y;
    const int b = bh >> 4, h = bh & 15;

    const float* Vg = g_qkv + (size_t)(2 * kB * kH + bh) * kN * kD
                    + (size_t)tk0 * kD;
    const float* Pg = g_attnP + (size_t)bh * (kD * kD);

#pragma unroll
    for (int i = 0; i < 4; ++i) {
        const int f = t + i * 256;
        const int row = f >> 4;
        const int e4 = (f & 15) * 4;
        const int kp = e4 >> 1;
        float4 v = *(const float4*)(Vg + (size_t)row * kD + e4);
        split2pack_bf(v.x, v.y, VH[kp][row], VL[kp][row]);
        split2pack_bf(v.z, v.w, VH[kp + 1][row], VL[kp + 1][row]);
        float4 p = *(const float4*)(Pg + row * kD + e4);
        split2pack_bf(p.x, p.y, PH[kp][row], PL[kp][row]);
        split2pack_bf(p.z, p.w, PH[kp + 1][row], PL[kp + 1][row]);
    }
    __syncthreads();

    float acc[2][2][4];
#pragma unroll
    for (int i = 0; i < 2; ++i)
#pragma unroll
        for (int j = 0; j < 2; ++j)
#pragma unroll
            for (int q = 0; q < 4; ++q) acc[i][j][q] = 0.f;

#pragma unroll
    for (int s = 0; s < 4; ++s) {
        const int base = 8 * s;
        unsigned aH[2][4], aL[2][4], bH[2][2], bL[2][2];
#pragma unroll
        for (int mt = 0; mt < 2; ++mt) {
            const int mr = wm + mt * 16 + r;
            aH[mt][0] = VH[base + c][mr];     aH[mt][1] = VH[base + c][mr + 8];
            aH[mt][2] = VH[base + c + 4][mr]; aH[mt][3] = VH[base + c + 4][mr + 8];
            aL[mt][0] = VL[base + c][mr];     aL[mt][1] = VL[base + c][mr + 8];
            aL[mt][2] = VL[base + c + 4][mr]; aL[mt][3] = VL[base + c + 4][mr + 8];
        }
#pragma unroll
        for (int nt = 0; nt < 2; ++nt) {
            const int nr = wn + nt * 8 + r;
            bH[nt][0] = PH[base + c][nr]; bH[nt][1] = PH[base + c + 4][nr];
            bL[nt][0] = PL[base + c][nr]; bL[nt][1] = PL[base + c + 4][nr];
        }
#pragma unroll
        for (int mt = 0; mt < 2; ++mt)
#pragma unroll
            for (int nt = 0; nt < 2; ++nt)
                mma3(acc[mt][nt], aH[mt], aL[mt],
                     bH[nt][0], bH[nt][1], bL[nt][0], bL[nt][1]);
    }

#pragma unroll
    for (int mt = 0; mt < 2; ++mt) {
#pragma unroll
        for (int nt = 0; nt < 2; ++nt) {
            const int tok = tk0 + wm + mt * 16 + r;
            const int ch = h * kD + wn + nt * 8 + 2 * c;
            const size_t i0 = (((size_t)b * kN + tok) * kC + ch) >> 1;
            const size_t i1 = (((size_t)b * kN + tok + 8) * kC + ch) >> 1;
            unsigned hw, lw;
            split2pack_h(acc[mt][nt][0], acc[mt][nt][1], hw, lw);
            ((unsigned*)g_outH)[i0] = hw;
            ((unsigned*)g_outL)[i0] = lw;
            split2pack_h(acc[mt][nt][2], acc[mt][nt][3], hw, lw);
            ((unsigned*)g_outH)[i1] = hw;
            ((unsigned*)g_outL)[i1] = lw;
        }
    }
}

// ---------------------------------------------------------------------------
extern "C" void kernel_launch(void* const* d_in, const int* in_sizes, int n_in,
                              void* d_out, int out_size)
{
    const float* x = nullptr;
    const float* Wqkv = nullptr;
    const float* Wproj = nullptr;
    const float* bproj = nullptr;
    const float* alpha = nullptr;
    for (int i = 0; i < n_in; ++i) {
        switch (in_sizes[i]) {
            case kM * kC:    x     = (const float*)d_in[i]; break;
            case kQKV * kC:  Wqkv  = (const float*)d_in[i]; break;
            case kC * kC:    Wproj = (const float*)d_in[i]; break;
            case kC:         bproj = (const float*)d_in[i]; break;
            case kH:         alpha = (const float*)d_in[i]; break;
            default: break;
        }
    }

    __half *xH, *xL, *wqH, *wqL, *wpH, *wpL, *oH, *oL;
    cudaGetSymbolAddress((void**)&xH, g_xH);     cudaGetSymbolAddress((void**)&xL, g_xL);
    cudaGetSymbolAddress((void**)&wqH, g_wqkvH); cudaGetSymbolAddress((void**)&wqL, g_wqkvL);
    cudaGetSymbolAddress((void**)&wpH, g_wprojH); cudaGetSymbolAddress((void**)&wpL, g_wprojL);
    cudaGetSymbolAddress((void**)&oH, g_outH);   cudaGetSymbolAddress((void**)&oL, g_outL);

    cudaFuncSetAttribute(f16x3_gemm_cp<OUT_QKV_HM>,
                         cudaFuncAttributeMaxDynamicSharedMemorySize, SMEM_GEMM);
    cudaFuncSetAttribute(f16x3_gemm_cp<OUT_PLAIN_BIAS>,
                         cudaFuncAttributeMaxDynamicSharedMemorySize, SMEM_GEMM);

    // 0) pre-split GEMM operands (fp16 hi/lo)
    {
        int n4 = kM * kC / 4;
        split_kernel<<<(n4 + 255) / 256, 256>>>(x, xH, xL, n4);
        n4 = kQKV * kC / 4;
        split_kernel<<<(n4 + 255) / 256, 256>>>(Wqkv, wqH, wqL, n4);
        n4 = kC * kC / 4;
        split_kernel<<<(n4 + 255) / 256, 256>>>(Wproj, wpH, wpL, n4);
    }

    // 1) QKV projection -> head-major qkv (3-term q,k; 2-term v)
    dim3 g1(kQKV / 128, kM / 128);
    f16x3_gemm_cp<OUT_QKV_HM><<<g1, 256, SMEM_GEMM>>>(
        xH, xL, wqH, wqL, nullptr, nullptr, kM, kQKV, kC);

    // 2) Channel-attention logits on tensor cores
    attn_logits_mma<<<dim3(kSplits, kB * kH), 256>>>();

    // 3) Softmax
    softmax_kernel<<<kB * kH * kD, kD>>>(alpha);

    // 4) P @ V^T on tensor cores (emits split fp16 out)
    pv_mma<<<dim3(kN / 64, kB * kH), 256>>>();

    // 5) Output projection + bias (2-term)
    dim3 g3(kC / 128, kM / 128);
    f16x3_gemm_cp<OUT_PLAIN_BIAS><<<g3, 256, SMEM_GEMM>>>(
        oH, oL, wpH, wpL, (float*)d_out, bproj, kM, kC, kC);
}

// round 15
// speedup vs baseline: 2.2209x; 1.4553x over previous
#include <cuda_runtime.h>
#include <cuda_fp16.h>
#include <cstdint>

// ---------------------------------------------------------------------------
// SpectralMSA channel attention — Round 15: Gram-matrix logits restructure.
//   K^T Q = Wk (x^T x) Wq^T  ->  q,k GEMMs eliminated.
//   G = x^T x per batch (symmetric: upper-tri tiles + mirror), 3-term fp16.
//   T = Wk G (3-term), logits = T Wq^T per head + fused softmax.
//   GEMM1 reduced to v only (2-term). pv + GEMM3 (2-term) unchanged.
//   All GEMMs: R11 pipeline (3-stage k32 cp.async, wait_group<1>, XOR swizzle).
// ---------------------------------------------------------------------------

namespace {
constexpr int kB = 4;
constexpr int kN = 4096;
constexpr int kC = 1024;
constexpr int kH = 16;
constexpr int kD = 64;
constexpr int kM = kB * kN;        // 16384
constexpr int kQKV = 3 * kC;       // 3072
}

// fp32 scratch (v stored head-major in the sel=2 region, layout as before)
__device__ float g_qkv[(size_t)3 * kB * kH * kN * kD];
__device__ float g_attnP[(size_t)kB * kH * kD * kD];
// split-fp16 operands
__device__ __half g_xH[(size_t)kM * kC],      g_xL[(size_t)kM * kC];
__device__ __half g_xtH[(size_t)kB * kC * kN], g_xtL[(size_t)kB * kC * kN];  // x^T per batch
__device__ __half g_wqkvH[(size_t)kQKV * kC], g_wqkvL[(size_t)kQKV * kC];
__device__ __half g_wprojH[(size_t)kC * kC],  g_wprojL[(size_t)kC * kC];
__device__ __half g_GH[(size_t)kB * kC * kC], g_GL[(size_t)kB * kC * kC];    // Gram
__device__ __half g_TH[(size_t)kB * kC * kC], g_TL[(size_t)kB * kC * kC];    // Wk G
__device__ __half g_outH[(size_t)kM * kC],    g_outL[(size_t)kM * kC];

// ---------------- low-level helpers ----------------------------------------
__device__ __forceinline__ void mma_f16_f32(float& d0, float& d1, float& d2, float& d3,
                                            unsigned a0, unsigned a1, unsigned a2, unsigned a3,
                                            unsigned b0, unsigned b1)
{
    asm volatile(
        "mma.sync.aligned.m16n8k16.row.col.f32.f16.f16.f32 "
        "{%0,%1,%2,%3},{%4,%5,%6,%7},{%8,%9},{%0,%1,%2,%3};"
        : "+f"(d0), "+f"(d1), "+f"(d2), "+f"(d3)
        : "r"(a0), "r"(a1), "r"(a2), "r"(a3), "r"(b0), "r"(b1));
}
__device__ __forceinline__ void split2pack_h(float a, float b, unsigned& h, unsigned& l)
{
    __half ha = __float2half_rn(a), hb = __float2half_rn(b);
    __half2 ph(ha, hb); h = *(unsigned*)&ph;
    __half2 pl(__float2half_rn(a - __half2float(ha)),
               __float2half_rn(b - __half2float(hb)));
    l = *(unsigned*)&pl;
}
__device__ __forceinline__ uint32_t smem_u32(const void* p) {
    uint32_t a;
    asm("{ .reg .u64 t; cvta.to.shared.u64 t, %1; cvt.u32.u64 %0, t; }"
        : "=r"(a) : "l"(p));
    return a;
}
__device__ __forceinline__ void cp16(uint32_t dst, const void* src) {
    asm volatile("cp.async.cg.shared.global [%0], [%1], 16;" :: "r"(dst), "l"(src));
}
__device__ __forceinline__ void cp_commit() {
    asm volatile("cp.async.commit_group;" ::: "memory");
}
template <int N>
__device__ __forceinline__ void cp_wait() {
    asm volatile("cp.async.wait_group %0;" :: "n"(N) : "memory");
}
__device__ __forceinline__ void ldsm4(unsigned* r, uint32_t addr) {
    asm volatile("ldmatrix.sync.aligned.m8n8.x4.shared.b16 {%0,%1,%2,%3}, [%4];"
                 : "=r"(r[0]), "=r"(r[1]), "=r"(r[2]), "=r"(r[3]) : "r"(addr));
}

// ---------------------------------------------------------------------------
__global__ void split_kernel(const float* __restrict__ src,
                             __half* __restrict__ hi,
                             __half* __restrict__ lo, int n4)
{
    int i = blockIdx.x * blockDim.x + threadIdx.x;
    if (i >= n4) return;
    float4 v = ((const float4*)src)[i];
    unsigned h0, h1, l0, l1;
    split2pack_h(v.x, v.y, h0, l0);
    split2pack_h(v.z, v.w, h1, l1);
    ((uint2*)hi)[i] = make_uint2(h0, h1);
    ((uint2*)lo)[i] = make_uint2(l0, l1);
}

// transpose + split: x [B*N, C] fp32 -> xt [B][C][N] fp16 hi/lo
__global__ __launch_bounds__(256)
void transpose_split_kernel(const float* __restrict__ x)
{
    __shared__ float s[32][33];
    const int c0 = blockIdx.x * 32;
    const int n0 = blockIdx.y * 32;        // global token (never crosses batch)
    const int t = threadIdx.x;
    const int tc = t & 31, tr = t >> 5;    // tr 0..7

#pragma unroll
    for (int i = 0; i < 4; ++i) {
        const int row = tr + i * 8;
        s[row][tc] = x[(size_t)(n0 + row) * kC + c0 + tc];
    }
    __syncthreads();

    const int b = n0 >> 12;
    const int nb = n0 & 4095;
#pragma unroll
    for (int i = 0; i < 4; ++i) {
        const int cc = tr + i * 8;         // col within tile (channel)
        const float v = s[tc][cc];
        __half hv = __float2half_rn(v);
        const size_t o = ((size_t)b * kC + c0 + cc) * kN + nb + tc;
        g_xtH[o] = hv;
        g_xtL[o] = __float2half_rn(v - __half2float(hv));
    }
}

// ---------------------------------------------------------------------------
// Unified fp16-split GEMM (NT): 3-stage k32 cp.async ring, XOR swizzle.
// MODE 0: fp32 C + bias. MODE 1: write v head-major into g_qkv (sel=2).
// MODE 2: split fp16 out (CH/CL). NTERMS = 2 (HH+HL) or 3 (+LH).
// ---------------------------------------------------------------------------
namespace {
constexpr int ROWB   = 64;
constexpr int PLANE  = 128 * ROWB;       // 8192 B
constexpr int STAGEB = 4 * PLANE;        // 32768 B
constexpr int SMEM_GEMM = 3 * STAGEB;    // 98304 B
}

template <int MODE, int NTERMS>
__global__ __launch_bounds__(256)
void f16_gemm(const __half* __restrict__ AH, const __half* __restrict__ AL,
              const __half* __restrict__ BH, const __half* __restrict__ BL,
              float* __restrict__ C, const float* __restrict__ bias,
              __half* __restrict__ CH, __half* __restrict__ CL,
              int M, int N, int K,
              size_t aBatch, size_t bBatch, size_t cBatch)
{
    extern __shared__ char sm[];
    const uint32_t sbase = smem_u32(sm);

    const int z = blockIdx.z;
    AH += (size_t)z * aBatch; AL += (size_t)z * aBatch;
    BH += (size_t)z * bBatch; BL += (size_t)z * bBatch;

    const int t = threadIdx.x;
    const int warp = t >> 5, lane = t & 31;
    const int wm = (warp & 1) * 64;
    const int wn = (warp >> 1) * 32;
    const int m0 = blockIdx.y * 128, n0 = blockIdx.x * 128;

    const int lrowA = t >> 2, lcA = t & 3;
    const int lrowB = (t + 256) >> 2, lcB = (t + 256) & 3;
    const uint32_t dA = lrowA * ROWB + ((lcA ^ ((lrowA >> 1) & 3)) << 4);
    const uint32_t dB = lrowB * ROWB + ((lcB ^ ((lrowB >> 1) & 3)) << 4);

    const __half* pAH = AH + (size_t)m0 * K;
    const __half* pAL = AL + (size_t)m0 * K;
    const __half* pBH = BH + (size_t)n0 * K;
    const __half* pBL = BL + (size_t)n0 * K;

    auto load_stage = [&](uint32_t stoff, int k0) {
        const uint32_t s0 = sbase + stoff;
        const size_t gA = (size_t)lrowA * K + k0 + lcA * 8;
        const size_t gB = (size_t)lrowB * K + k0 + lcB * 8;
        cp16(s0 + dA,             pAH + gA);
        cp16(s0 + dB,             pAH + gB);
        if (NTERMS == 3) {
            cp16(s0 + PLANE + dA, pAL + gA);
            cp16(s0 + PLANE + dB, pAL + gB);
        }
        cp16(s0 + 2 * PLANE + dA, pBH + gA);
        cp16(s0 + 2 * PLANE + dB, pBH + gB);
        cp16(s0 + 3 * PLANE + dA, pBL + gA);
        cp16(s0 + 3 * PLANE + dB, pBL + gB);
    };

    float acc[4][4][4];
#pragma unroll
    for (int i = 0; i < 4; ++i)
#pragma unroll
        for (int j = 0; j < 4; ++j)
#pragma unroll
            for (int q = 0; q < 4; ++q) acc[i][j][q] = 0.f;

    const int quad = lane >> 3;
    const int l8   = lane & 7;
    const int roff = (quad & 1) * 8 + l8;
    const int kq   = quad >> 1;
    const int xk   = (roff >> 1) & 3;
    const uint32_t swz0 = (uint32_t)(((0 + kq) ^ xk) << 4);
    const uint32_t swz1 = (uint32_t)(((2 + kq) ^ xk) << 4);

    const int nch = K / 32;

    load_stage(0 * STAGEB, 0);  cp_commit();
    load_stage(1 * STAGEB, 32); cp_commit();

    for (int ch = 0; ch < nch; ch += 3) {
#pragma unroll
        for (int u = 0; u < 3; ++u) {
            const int cc = ch + u;
            if (cc >= nch) break;

            cp_wait<1>();
            __syncthreads();

            if (cc + 2 < nch)
                load_stage((uint32_t)(((u + 2) % 3) * STAGEB), (cc + 2) * 32);
            cp_commit();

            const uint32_t sb = sbase + (uint32_t)(u * STAGEB);
#pragma unroll
            for (int s = 0; s < 2; ++s) {
                const uint32_t swz = s ? swz1 : swz0;
                unsigned aH[4][4], aL[4][4];
#pragma unroll
                for (int mt = 0; mt < 4; ++mt) {
                    const uint32_t ra = sb + (wm + mt * 16 + roff) * ROWB + swz;
                    ldsm4(aH[mt], ra);
                    if (NTERMS == 3) ldsm4(aL[mt], ra + PLANE);
                }
                unsigned bfH[2][4], bfL[2][4];
#pragma unroll
                for (int pt = 0; pt < 2; ++pt) {
                    const uint32_t rb = sb + 2 * PLANE
                                      + (wn + pt * 16 + roff) * ROWB + swz;
                    ldsm4(bfH[pt], rb);
                    ldsm4(bfL[pt], rb + PLANE);
                }
#pragma unroll
                for (int mt = 0; mt < 4; ++mt)
#pragma unroll
                    for (int nt = 0; nt < 4; ++nt) {
                        const int pt = nt >> 1, hi = nt & 1;
                        mma_f16_f32(acc[mt][nt][0], acc[mt][nt][1],
                                    acc[mt][nt][2], acc[mt][nt][3],
                                    aH[mt][0], aH[mt][1], aH[mt][2], aH[mt][3],
                                    bfH[pt][hi], bfH[pt][2 + hi]);
                    }
#pragma unroll
                for (int mt = 0; mt < 4; ++mt)
#pragma unroll
                    for (int nt = 0; nt < 4; ++nt) {
                        const int pt = nt >> 1, hi = nt & 1;
                        mma_f16_f32(acc[mt][nt][0], acc[mt][nt][1],
                                    acc[mt][nt][2], acc[mt][nt][3],
                                    aH[mt][0], aH[mt][1], aH[mt][2], aH[mt][3],
                                    bfL[pt][hi], bfL[pt][2 + hi]);
                    }
                if (NTERMS == 3) {
#pragma unroll
                    for (int mt = 0; mt < 4; ++mt)
#pragma unroll
                        for (int nt = 0; nt < 4; ++nt) {
                            const int pt = nt >> 1, hi = nt & 1;
                            mma_f16_f32(acc[mt][nt][0], acc[mt][nt][1],
                                        acc[mt][nt][2], acc[mt][nt][3],
                                        aL[mt][0], aL[mt][1], aL[mt][2], aL[mt][3],
                                        bfH[pt][hi], bfH[pt][2 + hi]);
                        }
                }
            }
        }
    }

    const int r = lane >> 2, c = lane & 3;
#pragma unroll
    for (int mt = 0; mt < 4; ++mt) {
#pragma unroll
        for (int nt = 0; nt < 4; ++nt) {
            const int m = m0 + wm + mt * 16 + r;
            const int n = n0 + wn + nt * 8 + c * 2;
            float2 v0 = make_float2(acc[mt][nt][0], acc[mt][nt][1]);
            float2 v1 = make_float2(acc[mt][nt][2], acc[mt][nt][3]);
            if (MODE == 1) {
                // v head-major: sel=2, h = n>>6, d = n&63, b = m>>12
                const int h = n >> 6, d = n & 63;
                const int b = m >> 12, ntk = m & 4095;
                float* dst = g_qkv + (((size_t)(2 * kB * kH) + b * kH + h) * kN
                                      + ntk) * kD + d;
                *(float2*)dst = v0;
                *(float2*)(dst + 8 * kC) = v1;   // token+8: +8*kN*? no:
            } else if (MODE == 2) {
                const size_t w0 = ((size_t)z * cBatch + (size_t)m * N + n) >> 1;
                const size_t w1 = ((size_t)z * cBatch + (size_t)(m + 8) * N + n) >> 1;
                unsigned hw, lw;
                split2pack_h(v0.x, v0.y, hw, lw);
                ((unsigned*)CH)[w0] = hw; ((unsigned*)CL)[w0] = lw;
                split2pack_h(v1.x, v1.y, hw, lw);
                ((unsigned*)CH)[w1] = hw; ((unsigned*)CL)[w1] = lw;
            } else {
                const float b0v = bias[n], b1v = bias[n + 1];
                v0.x += b0v; v0.y += b1v;
                v1.x += b0v; v1.y += b1v;
                *(float2*)(C + (size_t)m * N + n)       = v0;
                *(float2*)(C + (size_t)(m + 8) * N + n) = v1;
            }
        }
    }
}

// Fix for MODE 1 +8-row write (can't express inline above cleanly): dedicated
// v epilogue helper used instead of the buggy pointer math. Re-specialize:
template <>
__global__ __launch_bounds__(256)
void f16_gemm<1, 2>(const __half* __restrict__ AH, const __half* __restrict__ AL,
                    const __half* __restrict__ BH, const __half* __restrict__ BL,
                    float* __restrict__ C, const float* __restrict__ bias,
                    __half* __restrict__ CH, __half* __restrict__ CL,
                    int M, int N, int K,
                    size_t aBatch, size_t bBatch, size_t cBatch)
{
    extern __shared__ char sm[];
    const uint32_t sbase = smem_u32(sm);

    const int t = threadIdx.x;
    const int warp = t >> 5, lane = t & 31;
    const int wm = (warp & 1) * 64;
    const int wn = (warp >> 1) * 32;
    const int m0 = blockIdx.y * 128, n0 = blockIdx.x * 128;

    const int lrowA = t >> 2, lcA = t & 3;
    const int lrowB = (t + 256) >> 2, lcB = (t + 256) & 3;
    const uint32_t dA = lrowA * ROWB + ((lcA ^ ((lrowA >> 1) & 3)) << 4);
    const uint32_t dB = lrowB * ROWB + ((lcB ^ ((lrowB >> 1) & 3)) << 4);

    const __half* pAH = AH + (size_t)m0 * K;
    const __half* pBH = BH + (size_t)n0 * K;
    const __half* pBL = BL + (size_t)n0 * K;

    auto load_stage = [&](uint32_t stoff, int k0) {
        const uint32_t s0 = sbase + stoff;
        const size_t gA = (size_t)lrowA * K + k0 + lcA * 8;
        const size_t gB = (size_t)lrowB * K + k0 + lcB * 8;
        cp16(s0 + dA,             pAH + gA);
        cp16(s0 + dB,             pAH + gB);
        cp16(s0 + 2 * PLANE + dA, pBH + gA);
        cp16(s0 + 2 * PLANE + dB, pBH + gB);
        cp16(s0 + 3 * PLANE + dA, pBL + gA);
        cp16(s0 + 3 * PLANE + dB, pBL + gB);
    };

    float acc[4][4][4];
#pragma unroll
    for (int i = 0; i < 4; ++i)
#pragma unroll
        for (int j = 0; j < 4; ++j)
#pragma unroll
            for (int q = 0; q < 4; ++q) acc[i][j][q] = 0.f;

    const int quad = lane >> 3;
    const int l8   = lane & 7;
    const int roff = (quad & 1) * 8 + l8;
    const int kq   = quad >> 1;
    const int xk   = (roff >> 1) & 3;
    const uint32_t swz0 = (uint32_t)(((0 + kq) ^ xk) << 4);
    const uint32_t swz1 = (uint32_t)(((2 + kq) ^ xk) << 4);

    const int nch = K / 32;
    load_stage(0 * STAGEB, 0);  cp_commit();
    load_stage(1 * STAGEB, 32); cp_commit();

    for (int ch = 0; ch < nch; ch += 3) {
#pragma unroll
        for (int u = 0; u < 3; ++u) {
            const int cc = ch + u;
            if (cc >= nch) break;
            cp_wait<1>();
            __syncthreads();
            if (cc + 2 < nch)
                load_stage((uint32_t)(((u + 2) % 3) * STAGEB), (cc + 2) * 32);
            cp_commit();

            const uint32_t sb = sbase + (uint32_t)(u * STAGEB);
#pragma unroll
            for (int s = 0; s < 2; ++s) {
                const uint32_t swz = s ? swz1 : swz0;
                unsigned aH[4][4];
#pragma unroll
                for (int mt = 0; mt < 4; ++mt)
                    ldsm4(aH[mt], sb + (wm + mt * 16 + roff) * ROWB + swz);
                unsigned bfH[2][4], bfL[2][4];
#pragma unroll
                for (int pt = 0; pt < 2; ++pt) {
                    const uint32_t rb = sb + 2 * PLANE
                                      + (wn + pt * 16 + roff) * ROWB + swz;
                    ldsm4(bfH[pt], rb);
                    ldsm4(bfL[pt], rb + PLANE);
                }
#pragma unroll
                for (int mt = 0; mt < 4; ++mt)
#pragma unroll
                    for (int nt = 0; nt < 4; ++nt) {
                        const int pt = nt >> 1, hi = nt & 1;
                        mma_f16_f32(acc[mt][nt][0], acc[mt][nt][1],
                                    acc[mt][nt][2], acc[mt][nt][3],
                                    aH[mt][0], aH[mt][1], aH[mt][2], aH[mt][3],
                                    bfH[pt][hi], bfH[pt][2 + hi]);
                    }
#pragma unroll
                for (int mt = 0; mt < 4; ++mt)
#pragma unroll
                    for (int nt = 0; nt < 4; ++nt) {
                        const int pt = nt >> 1, hi = nt & 1;
                        mma_f16_f32(acc[mt][nt][0], acc[mt][nt][1],
                                    acc[mt][nt][2], acc[mt][nt][3],
                                    aH[mt][0], aH[mt][1], aH[mt][2], aH[mt][3],
                                    bfL[pt][hi], bfL[pt][2 + hi]);
                    }
            }
        }
    }

    const int r = lane >> 2, c = lane & 3;
#pragma unroll
    for (int mt = 0; mt < 4; ++mt) {
#pragma unroll
        for (int nt = 0; nt < 4; ++nt) {
            const int m = m0 + wm + mt * 16 + r;
            const int n = n0 + wn + nt * 8 + c * 2;
            const int h = n >> 6, d = n & 63;
            const int b = m >> 12;
            const int ntk = m & 4095;
            float* base = g_qkv + ((size_t)(2 * kB * kH) + b * kH + h)
                          * ((size_t)kN * kD) + (size_t)ntk * kD + d;
            *(float2*)base = make_float2(acc[mt][nt][0], acc[mt][nt][1]);
            *(float2*)(base + (size_t)8 * kD)
                = make_float2(acc[mt][nt][2], acc[mt][nt][3]);
        }
    }
}

// ---------------------------------------------------------------------------
// Gram GEMM: G_b = xt_b xt_b^T (NT, A=B=xt). Upper-tri tiles + mirror write.
// ---------------------------------------------------------------------------
__global__ __launch_bounds__(256)
void gram_gemm()
{
    extern __shared__ char sm[];
    const uint32_t sbase = smem_u32(sm);

    // map blockIdx.x (0..35) -> (by <= bx) in an 8x8 tile grid
    int rem = blockIdx.x, by = 0, len = 8;
    while (rem >= len) { rem -= len; ++by; --len; }
    const int bx = by + rem;
    const int b = blockIdx.z;
    const int m0 = by * 128, n0 = bx * 128;
    const int K = kN;

    const __half* AHp = g_xtH + (size_t)b * kC * kN;
    const __half* ALp = g_xtL + (size_t)b * kC * kN;

    const int t = threadIdx.x;
    const int warp = t >> 5, lane = t & 31;
    const int wm = (warp & 1) * 64;
    const int wn = (warp >> 1) * 32;

    const int lrowA = t >> 2, lcA = t & 3;
    const int lrowB = (t + 256) >> 2, lcB = (t + 256) & 3;
    const uint32_t dA = lrowA * ROWB + ((lcA ^ ((lrowA >> 1) & 3)) << 4);
    const uint32_t dB = lrowB * ROWB + ((lcB ^ ((lrowB >> 1) & 3)) << 4);

    const __half* pAH = AHp + (size_t)m0 * K;
    const __half* pAL = ALp + (size_t)m0 * K;
    const __half* pBH = AHp + (size_t)n0 * K;
    const __half* pBL = ALp + (size_t)n0 * K;

    auto load_stage = [&](uint32_t stoff, int k0) {
        const uint32_t s0 = sbase + stoff;
        const size_t gA = (size_t)lrowA * K + k0 + lcA * 8;
        const size_t gB = (size_t)lrowB * K + k0 + lcB * 8;
        cp16(s0 + dA,             pAH + gA);
        cp16(s0 + dB,             pAH + gB);
        cp16(s0 + PLANE + dA,     pAL + gA);
        cp16(s0 + PLANE + dB,     pAL + gB);
        cp16(s0 + 2 * PLANE + dA, pBH + gA);
        cp16(s0 + 2 * PLANE + dB, pBH + gB);
        cp16(s0 + 3 * PLANE + dA, pBL + gA);
        cp16(s0 + 3 * PLANE + dB, pBL + gB);
    };

    float acc[4][4][4];
#pragma unroll
    for (int i = 0; i < 4; ++i)
#pragma unroll
        for (int j = 0; j < 4; ++j)
#pragma unroll
            for (int q = 0; q < 4; ++q) acc[i][j][q] = 0.f;

    const int quad = lane >> 3;
    const int l8   = lane & 7;
    const int roff = (quad & 1) * 8 + l8;
    const int kq   = quad >> 1;
    const int xk   = (roff >> 1) & 3;
    const uint32_t swz0 = (uint32_t)(((0 + kq) ^ xk) << 4);
    const uint32_t swz1 = (uint32_t)(((2 + kq) ^ xk) << 4);

    const int nch = K / 32;
    load_stage(0 * STAGEB, 0);  cp_commit();
    load_stage(1 * STAGEB, 32); cp_commit();

    for (int ch = 0; ch < nch; ch += 3) {
#pragma unroll
        for (int u = 0; u < 3; ++u) {
            const int cc = ch + u;
            if (cc >= nch) break;
            cp_wait<1>();
            __syncthreads();
            if (cc + 2 < nch)
                load_stage((uint32_t)(((u + 2) % 3) * STAGEB), (cc + 2) * 32);
            cp_commit();

            const uint32_t sb = sbase + (uint32_t)(u * STAGEB);
#pragma unroll
            for (int s = 0; s < 2; ++s) {
                const uint32_t swz = s ? swz1 : swz0;
                unsigned aH[4][4], aL[4][4];
#pragma unroll
                for (int mt = 0; mt < 4; ++mt) {
                    const uint32_t ra = sb + (wm + mt * 16 + roff) * ROWB + swz;
                    ldsm4(aH[mt], ra);
                    ldsm4(aL[mt], ra + PLANE);
                }
                unsigned bfH[2][4], bfL[2][4];
#pragma unroll
                for (int pt = 0; pt < 2; ++pt) {
                    const uint32_t rb = sb + 2 * PLANE
                                      + (wn + pt * 16 + roff) * ROWB + swz;
                    ldsm4(bfH[pt], rb);
                    ldsm4(bfL[pt], rb + PLANE);
                }
#pragma unroll
                for (int mt = 0; mt < 4; ++mt)
#pragma unroll
                    for (int nt = 0; nt < 4; ++nt) {
                        const int pt = nt >> 1, hi = nt & 1;
                        mma_f16_f32(acc[mt][nt][0], acc[mt][nt][1],
                                    acc[mt][nt][2], acc[mt][nt][3],
                                    aH[mt][0], aH[mt][1], aH[mt][2], aH[mt][3],
                                    bfH[pt][hi], bfH[pt][2 + hi]);
                    }
#pragma unroll
                for (int mt = 0; mt < 4; ++mt)
#pragma unroll
                    for (int nt = 0; nt < 4; ++nt) {
                        const int pt = nt >> 1, hi = nt & 1;
                        mma_f16_f32(acc[mt][nt][0], acc[mt][nt][1],
                                    acc[mt][nt][2], acc[mt][nt][3],
                                    aH[mt][0], aH[mt][1], aH[mt][2], aH[mt][3],
                                    bfL[pt][hi], bfL[pt][2 + hi]);
                    }
#pragma unroll
                for (int mt = 0; mt < 4; ++mt)
#pragma unroll
                    for (int nt = 0; nt < 4; ++nt) {
                        const int pt = nt >> 1, hi = nt & 1;
                        mma_f16_f32(acc[mt][nt][0], acc[mt][nt][1],
                                    acc[mt][nt][2], acc[mt][nt][3],
                                    aL[mt][0], aL[mt][1], aL[mt][2], aL[mt][3],
                                    bfH[pt][hi], bfH[pt][2 + hi]);
                    }
            }
        }
    }

    const int r = lane >> 2, c = lane & 3;
    __half* GH = g_GH + (size_t)b * kC * kC;
    __half* GL = g_GL + (size_t)b * kC * kC;
#pragma unroll
    for (int mt = 0; mt < 4; ++mt) {
#pragma unroll
        for (int nt = 0; nt < 4; ++nt) {
            const int m = m0 + wm + mt * 16 + r;
            const int n = n0 + wn + nt * 8 + c * 2;
#pragma unroll
            for (int rr = 0; rr < 2; ++rr) {
                const int mm = m + rr * 8;
                const float va = acc[mt][nt][rr * 2];
                const float vb = acc[mt][nt][rr * 2 + 1];
                unsigned hw, lw;
                split2pack_h(va, vb, hw, lw);
                const size_t w = ((size_t)mm * kC + n) >> 1;
                ((unsigned*)GH)[w] = hw; ((unsigned*)GL)[w] = lw;
                // mirror (transpose) scalar writes
                __half ha = __float2half_rn(va);
                __half hb = __float2half_rn(vb);
                GH[(size_t)n * kC + mm] = ha;
                GL[(size_t)n * kC + mm] = __float2half_rn(va - __half2float(ha));
                GH[(size_t)(n + 1) * kC + mm] = hb;
                GL[(size_t)(n + 1) * kC + mm] = __float2half_rn(vb - __half2float(hb));
            }
        }
    }
}

// ---------------------------------------------------------------------------
// logits = T Wq^T per (b,h) + fused softmax. 64x64 out, K=1024, 3-term.
// ---------------------------------------------------------------------------
__global__ __launch_bounds__(256)
void logits_softmax(const float* __restrict__ alpha)
{
    __shared__ unsigned sA[4][32][72];   // TH, TL, QH, QL  [kpair][row]

    const int t = threadIdx.x;
    const int warp = t >> 5, lane = t & 31;
    const int wm = (warp & 1) * 32;      // d
    const int wn = (warp >> 1) * 16;     // e
    const int r = lane >> 2, c = lane & 3;
    const int bh = blockIdx.x;
    const int b = bh >> 4, h = bh & 15;

    const unsigned* srcs[4] = {
        (const unsigned*)g_TH + ((size_t)b * kC + h * 64) * (kC / 2),
        (const unsigned*)g_TL + ((size_t)b * kC + h * 64) * (kC / 2),
        (const unsigned*)g_wqkvH + (size_t)(h * 64) * (kC / 2),
        (const unsigned*)g_wqkvL + (size_t)(h * 64) * (kC / 2) };

    float acc[2][2][4];
#pragma unroll
    for (int i = 0; i < 2; ++i)
#pragma unroll
        for (int j = 0; j < 2; ++j)
#pragma unroll
            for (int q = 0; q < 4; ++q) acc[i][j][q] = 0.f;

    for (int kc = 0; kc < 16; ++kc) {
#pragma unroll
        for (int i = 0; i < 8; ++i) {
            const int idx = t + 256 * i;       // 0..2047
            const int arr = idx >> 9;
            const int rem = idx & 511;
            const int row = rem >> 3;
            const int q4  = rem & 7;
            uint4 v = ((const uint4*)(srcs[arr] + (size_t)row * (kC / 2)
                                      + kc * 32))[q4];
            sA[arr][q4 * 4 + 0][row] = v.x;
            sA[arr][q4 * 4 + 1][row] = v.y;
            sA[arr][q4 * 4 + 2][row] = v.z;
            sA[arr][q4 * 4 + 3][row] = v.w;
        }
        __syncthreads();

#pragma unroll
        for (int s = 0; s < 4; ++s) {
            const int base = 8 * s;
            unsigned aH[2][4], aL[2][4], bH[2][2], bL[2][2];
#pragma unroll
            for (int mt = 0; mt < 2; ++mt) {
                const int mr = wm + mt * 16 + r;
                aH[mt][0] = sA[0][base + c][mr];     aH[mt][1] = sA[0][base + c][mr + 8];
                aH[mt][2] = sA[0][base + c + 4][mr]; aH[mt][3] = sA[0][base + c + 4][mr + 8];
                aL[mt][0] = sA[1][base + c][mr];     aL[mt][1] = sA[1][base + c][mr + 8];
                aL[mt][2] = sA[1][base + c + 4][mr]; aL[mt][3] = sA[1][base + c + 4][mr + 8];
            }
#pragma unroll
            for (int nt = 0; nt < 2; ++nt) {
                const int nr = wn + nt * 8 + r;
                bH[nt][0] = sA[2][base + c][nr]; bH[nt][1] = sA[2][base + c + 4][nr];
                bL[nt][0] = sA[3][base + c][nr]; bL[nt][1] = sA[3][base + c + 4][nr];
            }
#pragma unroll
            for (int mt = 0; mt < 2; ++mt)
#pragma unroll
                for (int nt = 0; nt < 2; ++nt) {
                    mma_f16_f32(acc[mt][nt][0], acc[mt][nt][1], acc[mt][nt][2], acc[mt][nt][3],
                                aH[mt][0], aH[mt][1], aH[mt][2], aH[mt][3],
                                bL[nt][0], bL[nt][1]);
                    mma_f16_f32(acc[mt][nt][0], acc[mt][nt][1], acc[mt][nt][2], acc[mt][nt][3],
                                aL[mt][0], aL[mt][1], aL[mt][2], aL[mt][3],
                                bH[nt][0], bH[nt][1]);
                    mma_f16_f32(acc[mt][nt][0], acc[mt][nt][1], acc[mt][nt][2], acc[mt][nt][3],
                                aH[mt][0], aH[mt][1], aH[mt][2], aH[mt][3],
                                bH[nt][0], bH[nt][1]);
                }
        }
        __syncthreads();
    }

    // logits -> reused smem, fused softmax over e
    float* L = (float*)&sA[0][0][0];     // 64 x 65
#pragma unroll
    for (int mt = 0; mt < 2; ++mt)
#pragma unroll
        for (int nt = 0; nt < 2; ++nt) {
            const int dr = wm + mt * 16 + r;
            const int e0 = wn + nt * 8 + 2 * c;
            L[dr * 65 + e0]           = acc[mt][nt][0];
            L[dr * 65 + e0 + 1]       = acc[mt][nt][1];
            L[(dr + 8) * 65 + e0]     = acc[mt][nt][2];
            L[(dr + 8) * 65 + e0 + 1] = acc[mt][nt][3];
        }
    __syncthreads();

    if (t < 64) {
        const float inva = 1.0f / alpha[h];
        float mx = -1e30f;
        for (int e = 0; e < 64; ++e)
            mx = fmaxf(mx, L[t * 65 + e] * inva);
        float sum = 0.f;
        float* P = g_attnP + (size_t)bh * (kD * kD) + t * kD;
        for (int e = 0; e < 64; ++e) {
            const float ex = expf(L[t * 65 + e] * inva - mx);
            L[t * 65 + e] = ex;
            sum += ex;
        }
        const float inv = 1.0f / sum;
        for (int e = 0; e < 64; ++e)
            P[e] = L[t * 65 + e] * inv;
    }
}

// ---------------------------------------------------------------------------
// P @ V^T (bf16-free: fp16 3-term via split-on-stage) — R8-style, fp16 now.
// ---------------------------------------------------------------------------
__global__ __launch_bounds__(256)
void pv_mma()
{
    __shared__ unsigned VH[32][72], VL[32][72];
    __shared__ unsigned PH[32][72], PL[32][72];

    const int t = threadIdx.x;
    const int warp = t >> 5, lane = t & 31;
    const int wm = (warp & 1) * 32;
    const int wn = (warp >> 1) * 16;
    const int r = lane >> 2, c = lane & 3;
    const int tk0 = blockIdx.x * 64;
    const int bh = blockIdx.y;
    const int b = bh >> 4, h = bh & 15;

    const float* Vg = g_qkv + ((size_t)(2 * kB * kH) + bh) * ((size_t)kN * kD)
                    + (size_t)tk0 * kD;
    const float* Pg = g_attnP + (size_t)bh * (kD * kD);

#pragma unroll
    for (int i = 0; i < 4; ++i) {
        const int f = t + i * 256;
        const int row = f >> 4;
        const int e4 = (f & 15) * 4;
        const int kp = e4 >> 1;
        float4 v = *(const float4*)(Vg + (size_t)row * kD + e4);
        split2pack_h(v.x, v.y, VH[kp][row], VL[kp][row]);
        split2pack_h(v.z, v.w, VH[kp + 1][row], VL[kp + 1][row]);
        float4 p = *(const float4*)(Pg + row * kD + e4);
        split2pack_h(p.x, p.y, PH[kp][row], PL[kp][row]);
        split2pack_h(p.z, p.w, PH[kp + 1][row], PL[kp + 1][row]);
    }
    __syncthreads();

    float acc[2][2][4];
#pragma unroll
    for (int i = 0; i < 2; ++i)
#pragma unroll
        for (int j = 0; j < 2; ++j)
#pragma unroll
            for (int q = 0; q < 4; ++q) acc[i][j][q] = 0.f;

#pragma unroll
    for (int s = 0; s < 4; ++s) {
        const int base = 8 * s;
        unsigned aH[2][4], aL[2][4], bH[2][2], bL[2][2];
#pragma unroll
        for (int mt = 0; mt < 2; ++mt) {
            const int mr = wm + mt * 16 + r;
            aH[mt][0] = VH[base + c][mr];     aH[mt][1] = VH[base + c][mr + 8];
            aH[mt][2] = VH[base + c + 4][mr]; aH[mt][3] = VH[base + c + 4][mr + 8];
            aL[mt][0] = VL[base + c][mr];     aL[mt][1] = VL[base + c][mr + 8];
            aL[mt][2] = VL[base + c + 4][mr]; aL[mt][3] = VL[base + c + 4][mr + 8];
        }
#pragma unroll
        for (int nt = 0; nt < 2; ++nt) {
            const int nr = wn + nt * 8 + r;
            bH[nt][0] = PH[base + c][nr]; bH[nt][1] = PH[base + c + 4][nr];
            bL[nt][0] = PL[base + c][nr]; bL[nt][1] = PL[base + c + 4][nr];
        }
#pragma unroll
        for (int mt = 0; mt < 2; ++mt)
#pragma unroll
            for (int nt = 0; nt < 2; ++nt) {
                mma_f16_f32(acc[mt][nt][0], acc[mt][nt][1], acc[mt][nt][2], acc[mt][nt][3],
                            aH[mt][0], aH[mt][1], aH[mt][2], aH[mt][3], bL[nt][0], bL[nt][1]);
                mma_f16_f32(acc[mt][nt][0], acc[mt][nt][1], acc[mt][nt][2], acc[mt][nt][3],
                            aL[mt][0], aL[mt][1], aL[mt][2], aL[mt][3], bH[nt][0], bH[nt][1]);
                mma_f16_f32(acc[mt][nt][0], acc[mt][nt][1], acc[mt][nt][2], acc[mt][nt][3],
                            aH[mt][0], aH[mt][1], aH[mt][2], aH[mt][3], bH[nt][0], bH[nt][1]);
            }
    }

#pragma unroll
    for (int mt = 0; mt < 2; ++mt) {
#pragma unroll
        for (int nt = 0; nt < 2; ++nt) {
            const int tok = tk0 + wm + mt * 16 + r;
            const int ch = h * kD + wn + nt * 8 + 2 * c;
            const size_t i0 = (((size_t)b * kN + tok) * kC + ch) >> 1;
            const size_t i1 = (((size_t)b * kN + tok + 8) * kC + ch) >> 1;
            unsigned hw, lw;
            split2pack_h(acc[mt][nt][0], acc[mt][nt][1], hw, lw);
            ((unsigned*)g_outH)[i0] = hw;
            ((unsigned*)g_outL)[i0] = lw;
            split2pack_h(acc[mt][nt][2], acc[mt][nt][3], hw, lw);
            ((unsigned*)g_outH)[i1] = hw;
            ((unsigned*)g_outL)[i1] = lw;
        }
    }
}

// ---------------------------------------------------------------------------
extern "C" void kernel_launch(void* const* d_in, const int* in_sizes, int n_in,
                              void* d_out, int out_size)
{
    const float* x = nullptr;
    const float* Wqkv = nullptr;
    const float* Wproj = nullptr;
    const float* bproj = nullptr;
    const float* alpha = nullptr;
    for (int i = 0; i < n_in; ++i) {
        switch (in_sizes[i]) {
            case kM * kC:    x     = (const float*)d_in[i]; break;
            case kQKV * kC:  Wqkv  = (const float*)d_in[i]; break;
            case kC * kC:    Wproj = (const float*)d_in[i]; break;
            case kC:         bproj = (const float*)d_in[i]; break;
            case kH:         alpha = (const float*)d_in[i]; break;
            default: break;
        }
    }

    __half *xH, *xL, *wqH, *wqL, *wpH, *wpL, *oH, *oL, *gH, *gL, *tH, *tL;
    cudaGetSymbolAddress((void**)&xH, g_xH);     cudaGetSymbolAddress((void**)&xL, g_xL);
    cudaGetSymbolAddress((void**)&wqH, g_wqkvH); cudaGetSymbolAddress((void**)&wqL, g_wqkvL);
    cudaGetSymbolAddress((void**)&wpH, g_wprojH); cudaGetSymbolAddress((void**)&wpL, g_wprojL);
    cudaGetSymbolAddress((void**)&oH, g_outH);   cudaGetSymbolAddress((void**)&oL, g_outL);
    cudaGetSymbolAddress((void**)&gH, g_GH);     cudaGetSymbolAddress((void**)&gL, g_GL);
    cudaGetSymbolAddress((void**)&tH, g_TH);     cudaGetSymbolAddress((void**)&tL, g_TL);

    cudaFuncSetAttribute(f16_gemm<0, 2>, cudaFuncAttributeMaxDynamicSharedMemorySize, SMEM_GEMM);
    cudaFuncSetAttribute(f16_gemm<1, 2>, cudaFuncAttributeMaxDynamicSharedMemorySize, SMEM_GEMM);
    cudaFuncSetAttribute(f16_gemm<2, 3>, cudaFuncAttributeMaxDynamicSharedMemorySize, SMEM_GEMM);
    cudaFuncSetAttribute(gram_gemm,      cudaFuncAttributeMaxDynamicSharedMemorySize, SMEM_GEMM);

    // 0) splits + transpose-split
    {
        int n4 = kM * kC / 4;
        split_kernel<<<(n4 + 255) / 256, 256>>>(x, xH, xL, n4);
        n4 = kQKV * kC / 4;
        split_kernel<<<(n4 + 255) / 256, 256>>>(Wqkv, wqH, wqL, n4);
        n4 = kC * kC / 4;
        split_kernel<<<(n4 + 255) / 256, 256>>>(Wproj, wpH, wpL, n4);
        transpose_split_kernel<<<dim3(kC / 32, kM / 32), 256>>>(x);
    }

    // 1) v projection (2-term) -> head-major v in g_qkv
    f16_gemm<1, 2><<<dim3(kC / 128, kM / 128), 256, SMEM_GEMM>>>(
        xH, xL, wqH + (size_t)2048 * kC, wqL + (size_t)2048 * kC,
        nullptr, nullptr, nullptr, nullptr, kM, kC, kC, 0, 0, 0);

    // 2) Gram: G_b = x_b^T x_b (upper-tri + mirror), 3-term
    gram_gemm<<<dim3(36, 1, kB), 256, SMEM_GEMM>>>();

    // 3) T_b = Wk G_b (3-term, split out)
    f16_gemm<2, 3><<<dim3(kC / 128, kC / 128, kB), 256, SMEM_GEMM>>>(
        wqH + (size_t)1024 * kC, wqL + (size_t)1024 * kC, gH, gL,
        nullptr, nullptr, tH, tL, kC, kC, kC,
        0, (size_t)kC * kC, (size_t)kC * kC);

    // 4) logits = T Wq^T per head + fused softmax -> g_attnP
    logits_softmax<<<kB * kH, 256>>>(alpha);

    // 5) P @ V^T (emits split fp16 out)
    pv_mma<<<dim3(kN / 64, kB * kH), 256>>>();

    // 6) Output projection + bias (2-term)
    f16_gemm<0, 2><<<dim3(kC / 128, kM / 128), 256, SMEM_GEMM>>>(
        oH, oL, wpH, wpL, (float*)d_out, bproj, nullptr, nullptr,
        kM, kC, kC, 0, 0, 0);
}